// round 2
// baseline (speedup 1.0000x reference)
#include <cuda_runtime.h>
#include <math.h>

#define B_   16
#define WSZ  256
#define KF   64
#define HD   150
#define KS_  7

// ---------------- scratch (device globals; no allocation allowed) ----------------
__device__ float g_hcat[B_*WSZ*192];      // [b, t, 0:64]=xc, [64:128]=h_feat, [128:192]=h_temp
__device__ float g_g1f[B_*64*512];
__device__ float g_g2f[B_*64*512];
__device__ float g_g1t[B_*256*128];
__device__ float g_g2t[B_*256*128];
__device__ float g_xw[B_*256*450];        // reused by enc then dec
__device__ float g_hend[B_*HD];
__device__ float g_hrep[B_*WSZ*HD];
__device__ float g_dec[B_*WSZ*HD];
__device__ float g_cwt[KS_*64*64];        // conv_w transposed to [s][i][k]

__device__ __forceinline__ float sigm(float x) { return 1.f / (1.f + expf(-x)); }

// ---------------- conv weight transpose ----------------
__global__ void prep_cwt_kernel(const float* __restrict__ cw) {
    int idx = blockIdx.x * 256 + threadIdx.x;
    if (idx < KS_*64*64) {
        int k = idx / 448;
        int r = idx - k*448;
        int i = r / 7;
        int s = r - i*7;
        g_cwt[(s*64 + i)*64 + k] = cw[idx];
    }
}

// ---------------- conv1d + bias + relu -> hcat cols [0:64] ----------------
__global__ void conv_kernel(const float* __restrict__ x, const float* __restrict__ cb) {
    __shared__ float xs[14*64];
    int b = blockIdx.y, w0 = blockIdx.x * 8;
    int tid = threadIdx.x;
    for (int idx = tid; idx < 14*64; idx += 512) {
        int row = idx >> 6, i = idx & 63;
        int wg = w0 + row - 3;
        xs[idx] = (wg >= 0 && wg < WSZ) ? x[(b*WSZ + wg)*64 + i] : 0.f;
    }
    __syncthreads();
    int wl = tid >> 6, k = tid & 63;
    float acc = __ldg(&cb[k]);
    #pragma unroll
    for (int s = 0; s < 7; s++) {
        const float* cwp = &g_cwt[(s*64)*64 + k];
        const float* xp  = &xs[(wl + s)*64];
        #pragma unroll
        for (int i = 0; i < 64; i++)
            acc += xp[i] * __ldg(&cwp[i*64]);
    }
    g_hcat[(b*WSZ + w0 + wl)*192 + k] = fmaxf(acc, 0.f);
}

// ---------------- generic strided fp32 GEMM: C[b][m][n] = sum_k A(b,m,k)*B(k,n) + bias[n] ----------------
__global__ void gemm_kernel(const float* __restrict__ A, int a_rs, int a_cs, int a_bs,
                            const float* __restrict__ Bm, int b_rs, int b_cs,
                            const float* __restrict__ bias,
                            float* __restrict__ C, int c_bs,
                            int M, int N, int K)
{
    __shared__ float As[16][64];
    __shared__ float Bs[16][64];
    int bIdx = blockIdx.z;
    int m0 = blockIdx.y * 64, n0 = blockIdx.x * 64;
    const float* Ab = A + (long long)bIdx * a_bs;
    float* Cb = C + (long long)bIdx * c_bs;
    int tid = threadIdx.x;
    int tx = tid & 15, ty = tid >> 4;
    float acc[4][4] = {};
    for (int k0 = 0; k0 < K; k0 += 16) {
        // stage A
        if (a_cs == 1) {
            #pragma unroll
            for (int l = 0; l < 4; l++) {
                int idx = tid + l*256;
                int mm = idx >> 4, kk = idx & 15;
                int m = m0 + mm, k = k0 + kk;
                As[kk][mm] = (m < M && k < K) ? Ab[m*a_rs + k] : 0.f;
            }
        } else {
            #pragma unroll
            for (int l = 0; l < 4; l++) {
                int idx = tid + l*256;
                int kk = idx >> 6, mm = idx & 63;
                int m = m0 + mm, k = k0 + kk;
                As[kk][mm] = (m < M && k < K) ? Ab[m*a_rs + k*a_cs] : 0.f;
            }
        }
        // stage B
        if (b_cs == 1) {
            #pragma unroll
            for (int l = 0; l < 4; l++) {
                int idx = tid + l*256;
                int kk = idx >> 6, nn = idx & 63;
                int n = n0 + nn, k = k0 + kk;
                Bs[kk][nn] = (n < N && k < K) ? Bm[k*b_rs + n] : 0.f;
            }
        } else {
            #pragma unroll
            for (int l = 0; l < 4; l++) {
                int idx = tid + l*256;
                int nn = idx >> 4, kk = idx & 15;
                int n = n0 + nn, k = k0 + kk;
                Bs[kk][nn] = (n < N && k < K) ? Bm[k*b_rs + n*b_cs] : 0.f;
            }
        }
        __syncthreads();
        #pragma unroll
        for (int kk = 0; kk < 16; kk++) {
            float4 av = *(const float4*)&As[kk][ty*4];
            float4 bv = *(const float4*)&Bs[kk][tx*4];
            float a_[4] = {av.x, av.y, av.z, av.w};
            float b_[4] = {bv.x, bv.y, bv.z, bv.w};
            #pragma unroll
            for (int i = 0; i < 4; i++)
                #pragma unroll
                for (int j = 0; j < 4; j++)
                    acc[i][j] += a_[i] * b_[j];
        }
        __syncthreads();
    }
    #pragma unroll
    for (int i = 0; i < 4; i++) {
        int m = m0 + ty*4 + i;
        if (m >= M) continue;
        #pragma unroll
        for (int j = 0; j < 4; j++) {
            int n = n0 + tx*4 + j;
            if (n >= N) continue;
            float bv = bias ? __ldg(&bias[n]) : 0.f;
            Cb[m*N + n] = acc[i][j] + bv;
        }
    }
}

// ---------------- feature GAT: nodes=64, F=512 (e-dim), writes hcat cols [64:128] ----------------
__global__ void gat_feat_kernel(const float* __restrict__ g1f, const float* __restrict__ g2f,
                                const float* __restrict__ fa, const float* __restrict__ fbias)
{
    extern __shared__ float sm[];
    float* xcs = sm;               // 256*65
    float* g1i = sm + 256*65;      // 512
    float* es  = g1i + 512;        // 64
    float* att = es + 64;          // 64
    int i = blockIdx.x, b = blockIdx.y;
    int tid = threadIdx.x, lane = tid & 31, warp = tid >> 5;

    for (int e = tid; e < 512; e += 256) g1i[e] = g1f[(b*64 + i)*512 + e];
    for (int idx = tid; idx < 256*64; idx += 256) {
        int f = idx >> 6, j = idx & 63;
        xcs[f*65 + j] = g_hcat[(b*WSZ + f)*192 + j];
    }
    __syncthreads();

    for (int j = warp; j < 64; j += 8) {
        const float* g2 = &g2f[(b*64 + j)*512];
        float s = 0.f;
        for (int e = lane; e < 512; e += 32) {
            float v = g1i[e] + __ldg(&g2[e]);
            v = v > 0.f ? v : 0.2f * v;
            s += v * __ldg(&fa[e]);
        }
        #pragma unroll
        for (int o = 16; o > 0; o >>= 1) s += __shfl_xor_sync(0xffffffffu, s, o);
        if (lane == 0) es[j] = s + __ldg(&fbias[i*64 + j]);
    }
    __syncthreads();

    if (tid < 32) {
        float v0 = es[tid], v1 = es[tid + 32];
        float m = fmaxf(v0, v1);
        #pragma unroll
        for (int o = 16; o > 0; o >>= 1) m = fmaxf(m, __shfl_xor_sync(0xffffffffu, m, o));
        float e0 = expf(v0 - m), e1 = expf(v1 - m);
        float ss = e0 + e1;
        #pragma unroll
        for (int o = 16; o > 0; o >>= 1) ss += __shfl_xor_sync(0xffffffffu, ss, o);
        float inv = 1.f / ss;
        att[tid] = e0 * inv;
        att[tid + 32] = e1 * inv;
    }
    __syncthreads();

    int f = tid;
    float o = 0.f;
    #pragma unroll
    for (int j = 0; j < 64; j++) o += att[j] * xcs[f*65 + j];
    g_hcat[(b*WSZ + f)*192 + 64 + i] = sigm(o);
}

// ---------------- temporal GAT: nodes=256, F=128 (e-dim), writes hcat cols [128:192] ----------------
__global__ void gat_temp_kernel(const float* __restrict__ g1t, const float* __restrict__ g2t,
                                const float* __restrict__ ta, const float* __restrict__ tbias)
{
    __shared__ float g1i[128];
    __shared__ float es[256];
    __shared__ float att[256];
    __shared__ float part[256];
    __shared__ float redm[8];
    __shared__ float reds[8];
    int i = blockIdx.x, b = blockIdx.y;
    int tid = threadIdx.x, lane = tid & 31, warp = tid >> 5;

    if (tid < 128) g1i[tid] = g1t[(b*WSZ + i)*128 + tid];
    __syncthreads();

    for (int jj = 0; jj < 32; jj++) {
        int j = warp*32 + jj;
        const float* g2 = &g2t[(b*WSZ + j)*128];
        float s = 0.f;
        #pragma unroll
        for (int q = 0; q < 4; q++) {
            int e = lane + q*32;
            float v = g1i[e] + __ldg(&g2[e]);
            v = v > 0.f ? v : 0.2f * v;
            s += v * __ldg(&ta[e]);
        }
        #pragma unroll
        for (int o = 16; o > 0; o >>= 1) s += __shfl_xor_sync(0xffffffffu, s, o);
        if (lane == 0) es[j] = s + __ldg(&tbias[i*256 + j]);
    }
    __syncthreads();

    // softmax over 256 j
    float v = es[tid];
    float m = v;
    #pragma unroll
    for (int o = 16; o > 0; o >>= 1) m = fmaxf(m, __shfl_xor_sync(0xffffffffu, m, o));
    if (lane == 0) redm[warp] = m;
    __syncthreads();
    float bm = fmaxf(fmaxf(fmaxf(redm[0], redm[1]), fmaxf(redm[2], redm[3])),
                     fmaxf(fmaxf(redm[4], redm[5]), fmaxf(redm[6], redm[7])));
    float p = expf(v - bm);
    float s2 = p;
    #pragma unroll
    for (int o = 16; o > 0; o >>= 1) s2 += __shfl_xor_sync(0xffffffffu, s2, o);
    if (lane == 0) reds[warp] = s2;
    __syncthreads();
    float tot = reds[0]+reds[1]+reds[2]+reds[3]+reds[4]+reds[5]+reds[6]+reds[7];
    att[tid] = p / tot;
    __syncthreads();

    // out[f] = sigmoid(sum_j att[j] * xc[b,j,f])
    int pI = tid >> 6, f = tid & 63;
    float o = 0.f;
    for (int jj = 0; jj < 64; jj++) {
        int j = pI*64 + jj;
        o += att[j] * g_hcat[(b*WSZ + j)*192 + f];
    }
    part[tid] = o;
    __syncthreads();
    if (tid < 64) {
        float s = part[tid] + part[64 + tid] + part[128 + tid] + part[192 + tid];
        g_hcat[(b*WSZ + i)*192 + 128 + tid] = sigm(s);
    }
}

// ---------------- persistent GRU (one CTA per batch). Wh: 88 cols in regs + 62 cols in smem ----------------
#define KREG 88
#define KSM  62
#define GRU_SMEM_FLOATS (KSM*450 + 152 + 452 + 452 + 452)

__global__ __launch_bounds__(480, 1)
void gru_kernel(const float* __restrict__ Xw,     // [B,256,450] (includes bi)
                const float* __restrict__ Wh,     // [450,150]
                const float* __restrict__ bhv,    // [450]
                float* __restrict__ hend,         // [B,150] or null
                float* __restrict__ seqout)       // [B,256,150] or null
{
    extern __shared__ float sm[];
    float* Ws  = sm;                    // [KSM][450]
    float* hs  = sm + KSM*450;          // 152
    float* ys  = hs + 152;              // 452
    float* xws = ys + 452;              // 452
    float* bhs = xws + 452;             // 452
    int b = blockIdx.x;
    int t = threadIdx.x;

    float w[KREG];
    if (t < 450) {
        #pragma unroll
        for (int k = 0; k < KREG; k++) w[k] = __ldg(&Wh[t*150 + k]);
        bhs[t] = __ldg(&bhv[t]);
    }
    for (int idx = t; idx < KSM*450; idx += 480) {
        int k = idx / 450;
        int g = idx - k*450;
        Ws[idx] = __ldg(&Wh[g*150 + KREG + k]);
    }
    if (t < 152) hs[t] = 0.f;
    __syncthreads();

    const float* xwb = Xw + (long long)b * 256 * 450;
    for (int step = 0; step < 256; step++) {
        if (t < 450) {
            float xw = xwb[step*450 + t];
            float acc = bhs[t];
            #pragma unroll
            for (int k = 0; k < KREG; k++) acc += w[k] * hs[k];
            #pragma unroll
            for (int k = 0; k < KSM; k++) acc += Ws[k*450 + t] * hs[KREG + k];
            ys[t] = acc;
            xws[t] = xw;
        }
        __syncthreads();
        if (t < 150) {
            float r = sigm(xws[t]       + ys[t]);
            float z = sigm(xws[150 + t] + ys[150 + t]);
            float n = tanhf(xws[300 + t] + r * ys[300 + t]);
            float h = (1.f - z) * n + z * hs[t];
            hs[t] = h;
            if (seqout) seqout[((long long)b*256 + step)*150 + t] = h;
        }
        __syncthreads();
    }
    if (hend && t < 150) hend[b*150 + t] = hs[t];
}

// ---------------- predictions head ----------------
__global__ void pred_kernel(const float* __restrict__ hend,
                            const float* __restrict__ f0w, const float* __restrict__ f0b,
                            const float* __restrict__ f1w, const float* __restrict__ f1b,
                            float* __restrict__ out)
{
    __shared__ float he[152];
    __shared__ float t0[152];
    int b = blockIdx.x, tid = threadIdx.x;
    if (tid < 150) he[tid] = hend[b*150 + tid];
    __syncthreads();
    if (tid < 150) {
        float s = __ldg(&f0b[tid]);
        for (int k = 0; k < 150; k++) s += he[k] * __ldg(&f0w[k*150 + tid]);
        t0[tid] = fmaxf(s, 0.f);
    }
    __syncthreads();
    if (tid < 64) {
        float s = __ldg(&f1b[tid]);
        for (int k = 0; k < 150; k++) s += t0[k] * __ldg(&f1w[k*64 + tid]);
        out[b*64 + tid] = s;
    }
}

// ---------------- h_rep: h_rep.flat[b][r] = h_end[b][r >> 8] (repeat+reshape quirk) ----------------
__global__ void hrep_kernel(const float* __restrict__ hend, float* __restrict__ hrep) {
    int idx = blockIdx.x * 256 + threadIdx.x;
    if (idx < B_*WSZ*HD) {
        int b = idx / (WSZ*HD);
        int r = idx - b*(WSZ*HD);
        hrep[idx] = hend[b*HD + (r >> 8)];
    }
}

// ---------------- launch ----------------
extern "C" void kernel_launch(void* const* d_in, const int* in_sizes, int n_in,
                              void* d_out, int out_size)
{
    (void)in_sizes; (void)n_in; (void)out_size;
    const float* x      = (const float*)d_in[0];
    const float* conv_w = (const float*)d_in[1];
    const float* conv_b = (const float*)d_in[2];
    const float* fW     = (const float*)d_in[3];
    const float* fb     = (const float*)d_in[4];
    const float* fa     = (const float*)d_in[5];
    const float* fbias  = (const float*)d_in[6];
    const float* tW     = (const float*)d_in[7];
    const float* tb     = (const float*)d_in[8];
    const float* ta     = (const float*)d_in[9];
    const float* tbias  = (const float*)d_in[10];
    const float* gWi    = (const float*)d_in[11];
    const float* gWh    = (const float*)d_in[12];
    const float* gbi    = (const float*)d_in[13];
    const float* gbh    = (const float*)d_in[14];
    const float* f0w    = (const float*)d_in[15];
    const float* f0b    = (const float*)d_in[16];
    const float* f1w    = (const float*)d_in[17];
    const float* f1b    = (const float*)d_in[18];
    const float* rWi    = (const float*)d_in[19];
    const float* rWh    = (const float*)d_in[20];
    const float* rbi    = (const float*)d_in[21];
    const float* rbh    = (const float*)d_in[22];
    const float* rfw    = (const float*)d_in[23];
    const float* rfb    = (const float*)d_in[24];
    float* out = (float*)d_out;

    float *hcat, *g1f, *g2f, *g1t, *g2t, *xw, *hend, *hrep, *dec;
    cudaGetSymbolAddress((void**)&hcat, g_hcat);
    cudaGetSymbolAddress((void**)&g1f,  g_g1f);
    cudaGetSymbolAddress((void**)&g2f,  g_g2f);
    cudaGetSymbolAddress((void**)&g1t,  g_g1t);
    cudaGetSymbolAddress((void**)&g2t,  g_g2t);
    cudaGetSymbolAddress((void**)&xw,   g_xw);
    cudaGetSymbolAddress((void**)&hend, g_hend);
    cudaGetSymbolAddress((void**)&hrep, g_hrep);
    cudaGetSymbolAddress((void**)&dec,  g_dec);

    const int gat_smem = (256*65 + 512 + 64 + 64) * 4;
    const int gru_smem = GRU_SMEM_FLOATS * 4;
    cudaFuncSetAttribute(gat_feat_kernel, cudaFuncAttributeMaxDynamicSharedMemorySize, gat_smem);
    cudaFuncSetAttribute(gru_kernel, cudaFuncAttributeMaxDynamicSharedMemorySize, gru_smem);

    // 1. conv weight transpose + conv -> hcat[:, :, 0:64]
    prep_cwt_kernel<<<(KS_*64*64 + 255)/256, 256>>>(conv_w);
    conv_kernel<<<dim3(32, 16), 512>>>(x, conv_b);

    // 2. feature GAT projections: [64,256]@[256,512] per batch
    gemm_kernel<<<dim3(8, 1, 16), 256>>>(hcat, 1, 192, 256*192, fW,          512, 1, nullptr, g1f, 64*512, 64, 512, 256);
    gemm_kernel<<<dim3(8, 1, 16), 256>>>(hcat, 1, 192, 256*192, fW + 256*512, 512, 1, fb,     g2f, 64*512, 64, 512, 256);
    // 3. temporal GAT projections: [256,64]@[64,128] per batch
    gemm_kernel<<<dim3(2, 4, 16), 256>>>(hcat, 192, 1, 256*192, tW,          128, 1, nullptr, g1t, 256*128, 256, 128, 64);
    gemm_kernel<<<dim3(2, 4, 16), 256>>>(hcat, 192, 1, 256*192, tW + 64*128,  128, 1, tb,     g2t, 256*128, 256, 128, 64);

    // 4/5. attention + aggregation -> hcat[64:128], hcat[128:192]
    gat_feat_kernel<<<dim3(64, 16), 256, gat_smem>>>(g1f, g2f, fa, fbias);
    gat_temp_kernel<<<dim3(256, 16), 256>>>(g1t, g2t, ta, tbias);

    // 6. encoder xW = hcat @ gWi^T + gbi : [256,192]@[192,450]
    gemm_kernel<<<dim3(8, 4, 16), 256>>>(hcat, 192, 1, 256*192, gWi, 1, 192, gbi, xw, 256*450, 256, 450, 192);
    // 7. encoder GRU -> h_end
    gru_kernel<<<16, 480, gru_smem>>>(xw, gWh, gbh, hend, nullptr);
    // 8. predictions
    pred_kernel<<<16, 192>>>(hend, f0w, f0b, f1w, f1b, out);
    // 9. h_rep
    hrep_kernel<<<(B_*WSZ*HD + 255)/256, 256>>>(hend, hrep);
    // 10. decoder xW = h_rep @ rWi^T + rbi : [256,150]@[150,450]
    gemm_kernel<<<dim3(8, 4, 16), 256>>>(hrep, 150, 1, 256*150, rWi, 1, 150, rbi, xw, 256*450, 256, 450, 150);
    // 11. decoder GRU -> dec_out
    gru_kernel<<<16, 480, gru_smem>>>(xw, rWh, rbh, nullptr, dec);
    // 12. recons = dec_out @ rfw + rfb
    gemm_kernel<<<dim3(1, 4, 16), 256>>>(dec, 150, 1, 256*150, rfw, 64, 1, rfb, out + 1024, 256*64, 256, 64, 150);
}

// round 6
// speedup vs baseline: 1.0562x; 1.0562x over previous
#include <cuda_runtime.h>
#include <math.h>

#define B_   16
#define WSZ  256
#define KF   64
#define HD   150
#define KS_  7

// ---------------- scratch (device globals; no allocation allowed) ----------------
__device__ float g_hcat[B_*WSZ*192];      // [b, t, 0:64]=xc, [64:128]=h_feat, [128:192]=h_temp
__device__ float g_g1f[B_*64*512];
__device__ float g_g2f[B_*64*512];
__device__ float g_g1t[B_*256*128];
__device__ float g_g2t[B_*256*128];
__device__ float g_xw[B_*256*450];        // reused by enc then dec
__device__ float g_hend[B_*HD];
__device__ float g_hrep[B_*WSZ*HD];
__device__ float g_dec[B_*WSZ*HD];
__device__ float g_cwt[KS_*64*64];        // conv_w transposed to [s][i][k]

__device__ __forceinline__ float sigm(float x) { return 1.f / (1.f + expf(-x)); }

// packed f32x2 fma: d += a*b (elementwise on 2 packed floats in b64 regs)
__device__ __forceinline__ void ffma2(unsigned long long& d, unsigned long long a, unsigned long long b) {
    asm("fma.rn.f32x2 %0, %1, %2, %3;" : "=l"(d) : "l"(a), "l"(b), "l"(d));
}

// ---------------- conv weight transpose ----------------
__global__ void prep_cwt_kernel(const float* __restrict__ cw) {
    int idx = blockIdx.x * 256 + threadIdx.x;
    if (idx < KS_*64*64) {
        int k = idx / 448;
        int r = idx - k*448;
        int i = r / 7;
        int s = r - i*7;
        g_cwt[(s*64 + i)*64 + k] = cw[idx];
    }
}

// ---------------- conv1d + bias + relu -> hcat cols [0:64] ----------------
__global__ void conv_kernel(const float* __restrict__ x, const float* __restrict__ cb) {
    __shared__ float xs[14*64];
    int b = blockIdx.y, w0 = blockIdx.x * 8;
    int tid = threadIdx.x;
    for (int idx = tid; idx < 14*64; idx += 512) {
        int row = idx >> 6, i = idx & 63;
        int wg = w0 + row - 3;
        xs[idx] = (wg >= 0 && wg < WSZ) ? x[(b*WSZ + wg)*64 + i] : 0.f;
    }
    __syncthreads();
    int wl = tid >> 6, k = tid & 63;
    float acc = __ldg(&cb[k]);
    #pragma unroll
    for (int s = 0; s < 7; s++) {
        const float* cwp = &g_cwt[(s*64)*64 + k];
        const float* xp  = &xs[(wl + s)*64];
        #pragma unroll
        for (int i = 0; i < 64; i++)
            acc += xp[i] * __ldg(&cwp[i*64]);
    }
    g_hcat[(b*WSZ + w0 + wl)*192 + k] = fmaxf(acc, 0.f);
}

// ---------------- shared GEMM body: C[m][n] = sum_k A(m,k)*B(k,n) + bias[n] ----------------
__device__ __forceinline__ void gemm_body(const float* __restrict__ Ab, int a_rs, int a_cs,
                                          const float* __restrict__ Bm, int b_rs, int b_cs,
                                          const float* __restrict__ bias,
                                          float* __restrict__ Cb,
                                          int M, int N, int K, int m0, int n0,
                                          float As[16][64], float Bs[16][64])
{
    int tid = threadIdx.x;
    int tx = tid & 15, ty = tid >> 4;
    float acc[4][4] = {};
    for (int k0 = 0; k0 < K; k0 += 16) {
        if (a_cs == 1) {
            #pragma unroll
            for (int l = 0; l < 4; l++) {
                int idx = tid + l*256;
                int mm = idx >> 4, kk = idx & 15;
                int m = m0 + mm, k = k0 + kk;
                As[kk][mm] = (m < M && k < K) ? Ab[m*a_rs + k] : 0.f;
            }
        } else {
            #pragma unroll
            for (int l = 0; l < 4; l++) {
                int idx = tid + l*256;
                int kk = idx >> 6, mm = idx & 63;
                int m = m0 + mm, k = k0 + kk;
                As[kk][mm] = (m < M && k < K) ? Ab[m*a_rs + k*a_cs] : 0.f;
            }
        }
        if (b_cs == 1) {
            #pragma unroll
            for (int l = 0; l < 4; l++) {
                int idx = tid + l*256;
                int kk = idx >> 6, nn = idx & 63;
                int n = n0 + nn, k = k0 + kk;
                Bs[kk][nn] = (n < N && k < K) ? Bm[k*b_rs + n] : 0.f;
            }
        } else {
            #pragma unroll
            for (int l = 0; l < 4; l++) {
                int idx = tid + l*256;
                int nn = idx >> 4, kk = idx & 15;
                int n = n0 + nn, k = k0 + kk;
                Bs[kk][nn] = (n < N && k < K) ? Bm[k*b_rs + n*b_cs] : 0.f;
            }
        }
        __syncthreads();
        #pragma unroll
        for (int kk = 0; kk < 16; kk++) {
            float4 av = *(const float4*)&As[kk][ty*4];
            float4 bv = *(const float4*)&Bs[kk][tx*4];
            float a_[4] = {av.x, av.y, av.z, av.w};
            float b_[4] = {bv.x, bv.y, bv.z, bv.w};
            #pragma unroll
            for (int i = 0; i < 4; i++)
                #pragma unroll
                for (int j = 0; j < 4; j++)
                    acc[i][j] += a_[i] * b_[j];
        }
        __syncthreads();
    }
    #pragma unroll
    for (int i = 0; i < 4; i++) {
        int m = m0 + ty*4 + i;
        if (m >= M) continue;
        #pragma unroll
        for (int j = 0; j < 4; j++) {
            int n = n0 + tx*4 + j;
            if (n >= N) continue;
            float bv = bias ? __ldg(&bias[n]) : 0.f;
            Cb[m*N + n] = acc[i][j] + bv;
        }
    }
}

__global__ void gemm_kernel(const float* __restrict__ A, int a_rs, int a_cs, int a_bs,
                            const float* __restrict__ Bm, int b_rs, int b_cs,
                            const float* __restrict__ bias,
                            float* __restrict__ C, int c_bs,
                            int M, int N, int K)
{
    __shared__ float As[16][64];
    __shared__ float Bs[16][64];
    gemm_body(A + (long long)blockIdx.z * a_bs, a_rs, a_cs, Bm, b_rs, b_cs, bias,
              C + (long long)blockIdx.z * c_bs, M, N, K, blockIdx.y*64, blockIdx.x*64, As, Bs);
}

// ---------------- fused 4-way projection GEMM (g1f,g2f,g1t,g2t in ONE launch) ----------------
__global__ void proj4_kernel(const float* __restrict__ fW, const float* __restrict__ fb,
                             const float* __restrict__ tW, const float* __restrict__ tb)
{
    __shared__ float As[16][64];
    __shared__ float Bs[16][64];
    int task = blockIdx.x >> 7;
    int bid  = blockIdx.x & 127;
    if (task < 2) {
        // feature proj: per batch [64,256]@[256,512], A = xc^T (a_rs=1, a_cs=192)
        int bx = bid & 7, bz = bid >> 3;
        const float* Ab = g_hcat + bz*256*192;
        const float* Bm = (task == 0) ? fW : (fW + 256*512);
        const float* bias = (task == 0) ? nullptr : fb;
        float* Cb = ((task == 0) ? g_g1f : g_g2f) + bz*64*512;
        gemm_body(Ab, 1, 192, Bm, 512, 1, bias, Cb, 64, 512, 256, 0, bx*64, As, Bs);
    } else {
        // temporal proj: per batch [256,64]@[64,128], A = xc (a_rs=192, a_cs=1)
        int bx = bid & 1, by = (bid >> 1) & 3, bz = bid >> 3;
        const float* Ab = g_hcat + bz*256*192;
        const float* Bm = (task == 2) ? tW : (tW + 64*128);
        const float* bias = (task == 2) ? nullptr : tb;
        float* Cb = ((task == 2) ? g_g1t : g_g2t) + bz*256*128;
        gemm_body(Ab, 192, 1, Bm, 128, 1, bias, Cb, 256, 128, 64, by*64, bx*64, As, Bs);
    }
}

// ---------------- feature GAT: nodes=64, F=512 (e-dim), writes hcat cols [64:128] ----------------
__global__ void gat_feat_kernel(const float* __restrict__ g1f, const float* __restrict__ g2f,
                                const float* __restrict__ fa, const float* __restrict__ fbias)
{
    extern __shared__ float sm[];
    float* xcs = sm;               // 256*65
    float* g1i = sm + 256*65;      // 512
    float* es  = g1i + 512;        // 64
    float* att = es + 64;          // 64
    int i = blockIdx.x, b = blockIdx.y;
    int tid = threadIdx.x, lane = tid & 31, warp = tid >> 5;

    for (int e = tid; e < 512; e += 256) g1i[e] = g1f[(b*64 + i)*512 + e];
    for (int idx = tid; idx < 256*64; idx += 256) {
        int f = idx >> 6, j = idx & 63;
        xcs[f*65 + j] = g_hcat[(b*WSZ + f)*192 + j];
    }
    __syncthreads();

    for (int j = warp; j < 64; j += 8) {
        const float* g2 = &g2f[(b*64 + j)*512];
        float s = 0.f;
        for (int e = lane; e < 512; e += 32) {
            float v = g1i[e] + __ldg(&g2[e]);
            v = v > 0.f ? v : 0.2f * v;
            s += v * __ldg(&fa[e]);
        }
        #pragma unroll
        for (int o = 16; o > 0; o >>= 1) s += __shfl_xor_sync(0xffffffffu, s, o);
        if (lane == 0) es[j] = s + __ldg(&fbias[i*64 + j]);
    }
    __syncthreads();

    if (tid < 32) {
        float v0 = es[tid], v1 = es[tid + 32];
        float m = fmaxf(v0, v1);
        #pragma unroll
        for (int o = 16; o > 0; o >>= 1) m = fmaxf(m, __shfl_xor_sync(0xffffffffu, m, o));
        float e0 = expf(v0 - m), e1 = expf(v1 - m);
        float ss = e0 + e1;
        #pragma unroll
        for (int o = 16; o > 0; o >>= 1) ss += __shfl_xor_sync(0xffffffffu, ss, o);
        float inv = 1.f / ss;
        att[tid] = e0 * inv;
        att[tid + 32] = e1 * inv;
    }
    __syncthreads();

    int f = tid;
    float o = 0.f;
    #pragma unroll
    for (int j = 0; j < 64; j++) o += att[j] * xcs[f*65 + j];
    g_hcat[(b*WSZ + f)*192 + 64 + i] = sigm(o);
}

// ---------------- temporal GAT: nodes=256, F=128 (e-dim), writes hcat cols [128:192] ----------------
__global__ void gat_temp_kernel(const float* __restrict__ g1t, const float* __restrict__ g2t,
                                const float* __restrict__ ta, const float* __restrict__ tbias)
{
    __shared__ float g1i[128];
    __shared__ float es[256];
    __shared__ float att[256];
    __shared__ float part[256];
    __shared__ float redm[8];
    __shared__ float reds[8];
    int i = blockIdx.x, b = blockIdx.y;
    int tid = threadIdx.x, lane = tid & 31, warp = tid >> 5;

    if (tid < 128) g1i[tid] = g1t[(b*WSZ + i)*128 + tid];
    __syncthreads();

    for (int jj = 0; jj < 32; jj++) {
        int j = warp*32 + jj;
        const float* g2 = &g2t[(b*WSZ + j)*128];
        float s = 0.f;
        #pragma unroll
        for (int q = 0; q < 4; q++) {
            int e = lane + q*32;
            float v = g1i[e] + __ldg(&g2[e]);
            v = v > 0.f ? v : 0.2f * v;
            s += v * __ldg(&ta[e]);
        }
        #pragma unroll
        for (int o = 16; o > 0; o >>= 1) s += __shfl_xor_sync(0xffffffffu, s, o);
        if (lane == 0) es[j] = s + __ldg(&tbias[i*256 + j]);
    }
    __syncthreads();

    float v = es[tid];
    float m = v;
    #pragma unroll
    for (int o = 16; o > 0; o >>= 1) m = fmaxf(m, __shfl_xor_sync(0xffffffffu, m, o));
    if (lane == 0) redm[warp] = m;
    __syncthreads();
    float bm = fmaxf(fmaxf(fmaxf(redm[0], redm[1]), fmaxf(redm[2], redm[3])),
                     fmaxf(fmaxf(redm[4], redm[5]), fmaxf(redm[6], redm[7])));
    float p = expf(v - bm);
    float s2 = p;
    #pragma unroll
    for (int o = 16; o > 0; o >>= 1) s2 += __shfl_xor_sync(0xffffffffu, s2, o);
    if (lane == 0) reds[warp] = s2;
    __syncthreads();
    float tot = reds[0]+reds[1]+reds[2]+reds[3]+reds[4]+reds[5]+reds[6]+reds[7];
    att[tid] = p / tot;
    __syncthreads();

    int pI = tid >> 6, f = tid & 63;
    float o = 0.f;
    for (int jj = 0; jj < 64; jj++) {
        int j = pI*64 + jj;
        o += att[j] * g_hcat[(b*WSZ + j)*192 + f];
    }
    part[tid] = o;
    __syncthreads();
    if (tid < 64) {
        float s = part[tid] + part[64 + tid] + part[128 + tid] + part[192 + tid];
        g_hcat[(b*WSZ + i)*192 + 128 + tid] = sigm(s);
    }
}

// ---------------- persistent GRU, f32x2 packed. Wh row split: 96 floats in regs + 54 in smem ----------------
// packed pairs: 48 reg pairs (h[0..95]) + 13 ull2 smem pairs (h[96..147]) + 1 ull pair (h[148..149])
#define KRP 48            // reg pairs
#define WSV_N 13          // smem ulonglong2 entries per thread (26 pairs)
#define GRU_SMEM_BYTES (WSV_N*450*16 + 450*8 + (152 + 452 + 452 + 452)*4)

__global__ __launch_bounds__(480, 1)
void gru_kernel(const float* __restrict__ Xw,     // [B,256,450] (includes bi)
                const float* __restrict__ Wh,     // [450,150]
                const float* __restrict__ bhv,    // [450]
                float* __restrict__ hend,         // [B,150] or null
                float* __restrict__ seqout)       // [B,256,150] or null
{
    extern __shared__ float sm[];
    ulonglong2* WsV = (ulonglong2*)sm;                                  // [WSV_N][450]
    unsigned long long* Wlast = (unsigned long long*)(WsV + WSV_N*450); // [450]
    float* hs  = (float*)(Wlast + 450);   // 152 (16B-aligned)
    float* ys  = hs + 152;                // 452
    float* xws = ys + 452;                // 452
    float* bhs = xws + 452;               // 452
    int b = blockIdx.x;
    int t = threadIdx.x;

    unsigned long long w2[KRP];
    if (t < 450) {
        const unsigned long long* wrow = (const unsigned long long*)(Wh + t*150);
        #pragma unroll
        for (int k = 0; k < KRP; k++) w2[k] = wrow[k];
        #pragma unroll
        for (int q = 0; q < WSV_N; q++) {
            ulonglong2 v;
            v.x = wrow[KRP + 2*q];
            v.y = wrow[KRP + 2*q + 1];
            WsV[q*450 + t] = v;
        }
        Wlast[t] = wrow[74];
        bhs[t] = __ldg(&bhv[t]);
    }
    if (t < 152) hs[t] = 0.f;
    __syncthreads();

    const float* xwb = Xw + (long long)b * 256 * 450;
    for (int step = 0; step < 256; step++) {
        if (t < 450) {
            float xw = xwb[step*450 + t];
            unsigned long long acc0 = 0, acc1 = 0;   // packed (0,0)
            const ulonglong2* hp = (const ulonglong2*)hs;
            #pragma unroll
            for (int k = 0; k < KRP/2; k++) {        // pairs 0..47 from regs
                ulonglong2 h2 = hp[k];
                ffma2(acc0, w2[2*k],     h2.x);
                ffma2(acc1, w2[2*k + 1], h2.y);
            }
            #pragma unroll
            for (int q = 0; q < WSV_N; q++) {        // pairs 48..73 from smem
                ulonglong2 h2 = hp[KRP/2 + q];
                ulonglong2 wv = WsV[q*450 + t];
                ffma2(acc0, wv.x, h2.x);
                ffma2(acc1, wv.y, h2.y);
            }
            {                                        // pair 74 (h[148..149])
                unsigned long long hl = ((const unsigned long long*)hs)[74];
                ffma2(acc0, Wlast[t], hl);
            }
            float s = __uint_as_float((unsigned)acc0) + __uint_as_float((unsigned)(acc0 >> 32))
                    + __uint_as_float((unsigned)acc1) + __uint_as_float((unsigned)(acc1 >> 32));
            ys[t] = s + bhs[t];
            xws[t] = xw;
        }
        __syncthreads();
        if (t < 150) {
            float r = sigm(xws[t]       + ys[t]);
            float z = sigm(xws[150 + t] + ys[150 + t]);
            float n = tanhf(xws[300 + t] + r * ys[300 + t]);
            float h = (1.f - z) * n + z * hs[t];
            hs[t] = h;
            if (seqout) seqout[((long long)b*256 + step)*150 + t] = h;
        }
        __syncthreads();
    }
    if (hend && t < 150) hend[b*150 + t] = hs[t];
}

// ---------------- predictions head ----------------
__global__ void pred_kernel(const float* __restrict__ hend,
                            const float* __restrict__ f0w, const float* __restrict__ f0b,
                            const float* __restrict__ f1w, const float* __restrict__ f1b,
                            float* __restrict__ out)
{
    __shared__ float he[152];
    __shared__ float t0[152];
    int b = blockIdx.x, tid = threadIdx.x;
    if (tid < 150) he[tid] = hend[b*150 + tid];
    __syncthreads();
    if (tid < 150) {
        float s = __ldg(&f0b[tid]);
        for (int k = 0; k < 150; k++) s += he[k] * __ldg(&f0w[k*150 + tid]);
        t0[tid] = fmaxf(s, 0.f);
    }
    __syncthreads();
    if (tid < 64) {
        float s = __ldg(&f1b[tid]);
        for (int k = 0; k < 150; k++) s += t0[k] * __ldg(&f1w[k*64 + tid]);
        out[b*64 + tid] = s;
    }
}

// ---------------- h_rep: h_rep.flat[b][r] = h_end[b][r >> 8] (repeat+reshape quirk) ----------------
__global__ void hrep_kernel(const float* __restrict__ hend, float* __restrict__ hrep) {
    int idx = blockIdx.x * 256 + threadIdx.x;
    if (idx < B_*WSZ*HD) {
        int b = idx / (WSZ*HD);
        int r = idx - b*(WSZ*HD);
        hrep[idx] = hend[b*HD + (r >> 8)];
    }
}

// ---------------- launch ----------------
extern "C" void kernel_launch(void* const* d_in, const int* in_sizes, int n_in,
                              void* d_out, int out_size)
{
    (void)in_sizes; (void)n_in; (void)out_size;
    const float* x      = (const float*)d_in[0];
    const float* conv_w = (const float*)d_in[1];
    const float* conv_b = (const float*)d_in[2];
    const float* fW     = (const float*)d_in[3];
    const float* fb     = (const float*)d_in[4];
    const float* fa     = (const float*)d_in[5];
    const float* fbias  = (const float*)d_in[6];
    const float* tW     = (const float*)d_in[7];
    const float* tb     = (const float*)d_in[8];
    const float* ta     = (const float*)d_in[9];
    const float* tbias  = (const float*)d_in[10];
    const float* gWi    = (const float*)d_in[11];
    const float* gWh    = (const float*)d_in[12];
    const float* gbi    = (const float*)d_in[13];
    const float* gbh    = (const float*)d_in[14];
    const float* f0w    = (const float*)d_in[15];
    const float* f0b    = (const float*)d_in[16];
    const float* f1w    = (const float*)d_in[17];
    const float* f1b    = (const float*)d_in[18];
    const float* rWi    = (const float*)d_in[19];
    const float* rWh    = (const float*)d_in[20];
    const float* rbi    = (const float*)d_in[21];
    const float* rbh    = (const float*)d_in[22];
    const float* rfw    = (const float*)d_in[23];
    const float* rfb    = (const float*)d_in[24];
    float* out = (float*)d_out;

    float *hcat, *g1f, *g2f, *g1t, *g2t, *xw, *hend, *hrep, *dec;
    cudaGetSymbolAddress((void**)&hcat, g_hcat);
    cudaGetSymbolAddress((void**)&g1f,  g_g1f);
    cudaGetSymbolAddress((void**)&g2f,  g_g2f);
    cudaGetSymbolAddress((void**)&g1t,  g_g1t);
    cudaGetSymbolAddress((void**)&g2t,  g_g2t);
    cudaGetSymbolAddress((void**)&xw,   g_xw);
    cudaGetSymbolAddress((void**)&hend, g_hend);
    cudaGetSymbolAddress((void**)&hrep, g_hrep);
    cudaGetSymbolAddress((void**)&dec,  g_dec);

    const int gat_smem = (256*65 + 512 + 64 + 64) * 4;
    const int gru_smem = GRU_SMEM_BYTES;
    cudaFuncSetAttribute(gat_feat_kernel, cudaFuncAttributeMaxDynamicSharedMemorySize, gat_smem);
    cudaFuncSetAttribute(gru_kernel, cudaFuncAttributeMaxDynamicSharedMemorySize, gru_smem);

    // 1. conv weight transpose + conv -> hcat[:, :, 0:64]
    prep_cwt_kernel<<<(KS_*64*64 + 255)/256, 256>>>(conv_w);
    conv_kernel<<<dim3(32, 16), 512>>>(x, conv_b);

    // 2+3. all four GAT projections in ONE launch (512 CTAs)
    proj4_kernel<<<512, 256>>>(fW, fb, tW, tb);

    // 4/5. attention + aggregation -> hcat[64:128], hcat[128:192]
    gat_feat_kernel<<<dim3(64, 16), 256, gat_smem>>>(g1f, g2f, fa, fbias);
    gat_temp_kernel<<<dim3(256, 16), 256>>>(g1t, g2t, ta, tbias);

    // 6. encoder xW = hcat @ gWi^T + gbi : [256,192]@[192,450]
    gemm_kernel<<<dim3(8, 4, 16), 256>>>(hcat, 192, 1, 256*192, gWi, 1, 192, gbi, xw, 256*450, 256, 450, 192);
    // 7. encoder GRU -> h_end
    gru_kernel<<<16, 480, gru_smem>>>(xw, gWh, gbh, hend, nullptr);
    // 8. predictions
    pred_kernel<<<16, 192>>>(hend, f0w, f0b, f1w, f1b, out);
    // 9. h_rep
    hrep_kernel<<<(B_*WSZ*HD + 255)/256, 256>>>(hend, hrep);
    // 10. decoder xW = h_rep @ rWi^T + rbi : [256,150]@[150,450]
    gemm_kernel<<<dim3(8, 4, 16), 256>>>(hrep, 150, 1, 256*150, rWi, 1, 150, rbi, xw, 256*450, 256, 450, 150);
    // 11. decoder GRU -> dec_out
    gru_kernel<<<16, 480, gru_smem>>>(xw, rWh, rbh, nullptr, dec);
    // 12. recons = dec_out @ rfw + rfb
    gemm_kernel<<<dim3(1, 4, 16), 256>>>(dec, 150, 1, 256*150, rfw, 64, 1, rfb, out + 1024, 256*64, 256, 64, 150);
}

// round 13
// speedup vs baseline: 1.1410x; 1.0803x over previous
#include <cuda_runtime.h>
#include <math.h>

#define B_   16
#define WSZ  256
#define KF   64
#define HD   150
#define KS_  7

// ---------------- scratch (device globals; no allocation allowed) ----------------
__device__ float g_hcat[B_*WSZ*192];      // [b, t, 0:64]=xc, [64:128]=h_feat, [128:192]=h_temp
__device__ float g_g1f[B_*64*512];
__device__ float g_g2f[B_*64*512];
__device__ float g_g1t[B_*256*128];
__device__ float g_g2t[B_*256*128];
__device__ float g_attf[B_*64*64];        // feature GAT attention rows
__device__ float g_attt[B_*256*256];      // temporal GAT attention rows
__device__ float g_xw[B_*256*450];        // reused by enc then dec
__device__ float g_hend[B_*HD];
__device__ float g_hrep[B_*WSZ*HD];
__device__ float g_dec[B_*WSZ*HD];
__device__ float g_cwt[KS_*64*64];        // conv_w transposed to [s][i][k]

// fast transcendentals (MUFU-based, ~1e-6 accuracy; tolerance is 1e-3)
__device__ __forceinline__ float sigmf(float x) {
    return __fdividef(1.f, 1.f + __expf(-x));
}
__device__ __forceinline__ float tanhf_fast(float x) {
    x = fminf(fmaxf(x, -30.f), 30.f);
    float e = __expf(2.f * x);
    return __fdividef(e - 1.f, e + 1.f);
}

// packed f32x2 fma: d += a*b (elementwise on 2 packed floats in b64 regs)
__device__ __forceinline__ void ffma2(unsigned long long& d, unsigned long long a, unsigned long long b) {
    asm("fma.rn.f32x2 %0, %1, %2, %3;" : "=l"(d) : "l"(a), "l"(b), "l"(d));
}

// ---------------- conv weight transpose ----------------
__global__ void prep_cwt_kernel(const float* __restrict__ cw) {
    int idx = blockIdx.x * 256 + threadIdx.x;
    if (idx < KS_*64*64) {
        int k = idx / 448;
        int r = idx - k*448;
        int i = r / 7;
        int s = r - i*7;
        g_cwt[(s*64 + i)*64 + k] = cw[idx];
    }
}

// ---------------- conv1d + bias + relu -> hcat cols [0:64] ----------------
__global__ void conv_kernel(const float* __restrict__ x, const float* __restrict__ cb) {
    __shared__ float xs[14*64];
    int b = blockIdx.y, w0 = blockIdx.x * 8;
    int tid = threadIdx.x;
    for (int idx = tid; idx < 14*64; idx += 512) {
        int row = idx >> 6, i = idx & 63;
        int wg = w0 + row - 3;
        xs[idx] = (wg >= 0 && wg < WSZ) ? x[(b*WSZ + wg)*64 + i] : 0.f;
    }
    __syncthreads();
    int wl = tid >> 6, k = tid & 63;
    float acc = __ldg(&cb[k]);
    #pragma unroll
    for (int s = 0; s < 7; s++) {
        const float* cwp = &g_cwt[(s*64)*64 + k];
        const float* xp  = &xs[(wl + s)*64];
        #pragma unroll
        for (int i = 0; i < 64; i++)
            acc += xp[i] * __ldg(&cwp[i*64]);
    }
    g_hcat[(b*WSZ + w0 + wl)*192 + k] = fmaxf(acc, 0.f);
}

// ---------------- shared GEMM body with strided/activated epilogue ----------------
__device__ __forceinline__ void gemm_body(const float* __restrict__ Ab, int a_rs, int a_cs,
                                          const float* __restrict__ Bm, int b_rs, int b_cs,
                                          const float* __restrict__ bias,
                                          float* __restrict__ Cb,
                                          int M, int N, int K, int m0, int n0,
                                          int c_rs, int c_cs, int act,
                                          float As[16][64], float Bs[16][64])
{
    int tid = threadIdx.x;
    int tx = tid & 15, ty = tid >> 4;
    float acc[4][4] = {};
    for (int k0 = 0; k0 < K; k0 += 16) {
        if (a_cs == 1) {
            #pragma unroll
            for (int l = 0; l < 4; l++) {
                int idx = tid + l*256;
                int mm = idx >> 4, kk = idx & 15;
                int m = m0 + mm, k = k0 + kk;
                As[kk][mm] = (m < M && k < K) ? Ab[m*a_rs + k] : 0.f;
            }
        } else {
            #pragma unroll
            for (int l = 0; l < 4; l++) {
                int idx = tid + l*256;
                int kk = idx >> 6, mm = idx & 63;
                int m = m0 + mm, k = k0 + kk;
                As[kk][mm] = (m < M && k < K) ? Ab[m*a_rs + k*a_cs] : 0.f;
            }
        }
        if (b_cs == 1) {
            #pragma unroll
            for (int l = 0; l < 4; l++) {
                int idx = tid + l*256;
                int kk = idx >> 6, nn = idx & 63;
                int n = n0 + nn, k = k0 + kk;
                Bs[kk][nn] = (n < N && k < K) ? Bm[k*b_rs + n] : 0.f;
            }
        } else {
            #pragma unroll
            for (int l = 0; l < 4; l++) {
                int idx = tid + l*256;
                int nn = idx >> 4, kk = idx & 15;
                int n = n0 + nn, k = k0 + kk;
                Bs[kk][nn] = (n < N && k < K) ? Bm[k*b_rs + n*b_cs] : 0.f;
            }
        }
        __syncthreads();
        #pragma unroll
        for (int kk = 0; kk < 16; kk++) {
            float4 av = *(const float4*)&As[kk][ty*4];
            float4 bv = *(const float4*)&Bs[kk][tx*4];
            float a_[4] = {av.x, av.y, av.z, av.w};
            float b_[4] = {bv.x, bv.y, bv.z, bv.w};
            #pragma unroll
            for (int i = 0; i < 4; i++)
                #pragma unroll
                for (int j = 0; j < 4; j++)
                    acc[i][j] += a_[i] * b_[j];
        }
        __syncthreads();
    }
    #pragma unroll
    for (int i = 0; i < 4; i++) {
        int m = m0 + ty*4 + i;
        if (m >= M) continue;
        #pragma unroll
        for (int j = 0; j < 4; j++) {
            int n = n0 + tx*4 + j;
            if (n >= N) continue;
            float v = acc[i][j] + (bias ? __ldg(&bias[n]) : 0.f);
            if (act) v = sigmf(v);
            Cb[m*c_rs + n*c_cs] = v;
        }
    }
}

__global__ void gemm_kernel(const float* __restrict__ A, int a_rs, int a_cs, int a_bs,
                            const float* __restrict__ Bm, int b_rs, int b_cs,
                            const float* __restrict__ bias,
                            float* __restrict__ C, int c_bs,
                            int M, int N, int K)
{
    __shared__ float As[16][64];
    __shared__ float Bs[16][64];
    gemm_body(A + (long long)blockIdx.z * a_bs, a_rs, a_cs, Bm, b_rs, b_cs, bias,
              C + (long long)blockIdx.z * c_bs, M, N, K, blockIdx.y*64, blockIdx.x*64,
              N, 1, 0, As, Bs);
}

// ---------------- fused 4-way projection GEMM (g1f,g2f,g1t,g2t in ONE launch) ----------------
__global__ void proj4_kernel(const float* __restrict__ fW, const float* __restrict__ fb,
                             const float* __restrict__ tW, const float* __restrict__ tb)
{
    __shared__ float As[16][64];
    __shared__ float Bs[16][64];
    int task = blockIdx.x >> 7;
    int bid  = blockIdx.x & 127;
    if (task < 2) {
        int bx = bid & 7, bz = bid >> 3;
        const float* Ab = g_hcat + bz*256*192;
        const float* Bm = (task == 0) ? fW : (fW + 256*512);
        const float* bias = (task == 0) ? nullptr : fb;
        float* Cb = ((task == 0) ? g_g1f : g_g2f) + bz*64*512;
        gemm_body(Ab, 1, 192, Bm, 512, 1, bias, Cb, 64, 512, 256, 0, bx*64, 512, 1, 0, As, Bs);
    } else {
        int bx = bid & 1, by = (bid >> 1) & 3, bz = bid >> 3;
        const float* Ab = g_hcat + bz*256*192;
        const float* Bm = (task == 2) ? tW : (tW + 64*128);
        const float* bias = (task == 2) ? nullptr : tb;
        float* Cb = ((task == 2) ? g_g1t : g_g2t) + bz*256*128;
        gemm_body(Ab, 192, 1, Bm, 128, 1, bias, Cb, 256, 128, 64, by*64, bx*64, 128, 1, 0, As, Bs);
    }
}

// ---------------- feature GAT e + softmax: att rows -> g_attf ----------------
__global__ void gat_e_feat_kernel(const float* __restrict__ g1f, const float* __restrict__ g2f,
                                  const float* __restrict__ fa, const float* __restrict__ fbias)
{
    __shared__ float g1i[512];
    __shared__ float es[64];
    int i = blockIdx.x, b = blockIdx.y;
    int tid = threadIdx.x, lane = tid & 31, warp = tid >> 5;

    for (int e = tid; e < 512; e += 256) g1i[e] = g1f[(b*64 + i)*512 + e];
    __syncthreads();

    for (int j = warp; j < 64; j += 8) {
        const float* g2 = &g2f[(b*64 + j)*512];
        float s = 0.f;
        for (int e = lane; e < 512; e += 32) {
            float v = g1i[e] + __ldg(&g2[e]);
            v = v > 0.f ? v : 0.2f * v;
            s += v * __ldg(&fa[e]);
        }
        #pragma unroll
        for (int o = 16; o > 0; o >>= 1) s += __shfl_xor_sync(0xffffffffu, s, o);
        if (lane == 0) es[j] = s + __ldg(&fbias[i*64 + j]);
    }
    __syncthreads();

    if (tid < 32) {
        float v0 = es[tid], v1 = es[tid + 32];
        float m = fmaxf(v0, v1);
        #pragma unroll
        for (int o = 16; o > 0; o >>= 1) m = fmaxf(m, __shfl_xor_sync(0xffffffffu, m, o));
        float e0 = __expf(v0 - m), e1 = __expf(v1 - m);
        float ss = e0 + e1;
        #pragma unroll
        for (int o = 16; o > 0; o >>= 1) ss += __shfl_xor_sync(0xffffffffu, ss, o);
        float inv = __fdividef(1.f, ss);
        g_attf[(b*64 + i)*64 + tid]      = e0 * inv;
        g_attf[(b*64 + i)*64 + tid + 32] = e1 * inv;
    }
}

// ---------------- temporal GAT e + softmax: att rows -> g_attt ----------------
__global__ void gat_e_temp_kernel(const float* __restrict__ g1t, const float* __restrict__ g2t,
                                  const float* __restrict__ ta, const float* __restrict__ tbias)
{
    __shared__ float g1i[128];
    __shared__ float es[256];
    __shared__ float redm[8];
    __shared__ float reds[8];
    int i = blockIdx.x, b = blockIdx.y;
    int tid = threadIdx.x, lane = tid & 31, warp = tid >> 5;

    if (tid < 128) g1i[tid] = g1t[(b*WSZ + i)*128 + tid];
    __syncthreads();

    for (int jj = 0; jj < 32; jj++) {
        int j = warp*32 + jj;
        const float* g2 = &g2t[(b*WSZ + j)*128];
        float s = 0.f;
        #pragma unroll
        for (int q = 0; q < 4; q++) {
            int e = lane + q*32;
            float v = g1i[e] + __ldg(&g2[e]);
            v = v > 0.f ? v : 0.2f * v;
            s += v * __ldg(&ta[e]);
        }
        #pragma unroll
        for (int o = 16; o > 0; o >>= 1) s += __shfl_xor_sync(0xffffffffu, s, o);
        if (lane == 0) es[j] = s + __ldg(&tbias[i*256 + j]);
    }
    __syncthreads();

    float v = es[tid];
    float m = v;
    #pragma unroll
    for (int o = 16; o > 0; o >>= 1) m = fmaxf(m, __shfl_xor_sync(0xffffffffu, m, o));
    if (lane == 0) redm[warp] = m;
    __syncthreads();
    float bm = fmaxf(fmaxf(fmaxf(redm[0], redm[1]), fmaxf(redm[2], redm[3])),
                     fmaxf(fmaxf(redm[4], redm[5]), fmaxf(redm[6], redm[7])));
    float p = __expf(v - bm);
    float s2 = p;
    #pragma unroll
    for (int o = 16; o > 0; o >>= 1) s2 += __shfl_xor_sync(0xffffffffu, s2, o);
    if (lane == 0) reds[warp] = s2;
    __syncthreads();
    float tot = reds[0]+reds[1]+reds[2]+reds[3]+reds[4]+reds[5]+reds[6]+reds[7];
    g_attt[(b*WSZ + i)*256 + tid] = __fdividef(p, tot);
}

// ---------------- fused GAT aggregation GEMMs (feature + temporal, one launch) ----------------
// feature: out[b,i,f] = sigm(sum_j attf[b,i,j] * xc[b,f,j]) -> hcat[b,f,64+i]
// temporal: out[b,i,f] = sigm(sum_j attt[b,i,j] * xc[b,j,f]) -> hcat[b,i,128+f]
__global__ void gatagg_kernel()
{
    __shared__ float As[16][64];
    __shared__ float Bs[16][64];
    int bid = blockIdx.x;
    if (bid < 64) {
        int b = bid >> 2, fx = bid & 3;
        gemm_body(g_attf + b*64*64, 64, 1,
                  g_hcat + b*WSZ*192, 1, 192, nullptr,
                  g_hcat + b*WSZ*192 + 64,
                  64, 256, 64, 0, fx*64, 1, 192, 1, As, Bs);
    } else {
        int bid2 = bid - 64;
        int b = bid2 >> 2, my = bid2 & 3;
        gemm_body(g_attt + b*256*256, 256, 1,
                  g_hcat + b*WSZ*192, 192, 1, nullptr,
                  g_hcat + b*WSZ*192 + 128,
                  256, 64, 256, my*64, 0, 192, 1, 1, As, Bs);
    }
}

// ---------------- persistent GRU, f32x2 packed. Wh row split: 96 floats in regs + 54 in smem ----------------
#define KRP 48            // reg pairs
#define WSV_N 13          // smem ulonglong2 entries per thread (26 pairs)
#define GRU_SMEM_BYTES (WSV_N*450*16 + 450*8 + (152 + 452 + 452 + 452)*4)

__global__ __launch_bounds__(480, 1)
void gru_kernel(const float* __restrict__ Xw,     // [B,256,450] (includes bi)
                const float* __restrict__ Wh,     // [450,150]
                const float* __restrict__ bhv,    // [450]
                float* __restrict__ hend,         // [B,150] or null
                float* __restrict__ seqout)       // [B,256,150] or null
{
    extern __shared__ float sm[];
    ulonglong2* WsV = (ulonglong2*)sm;                                  // [WSV_N][450]
    unsigned long long* Wlast = (unsigned long long*)(WsV + WSV_N*450); // [450]
    float* hs  = (float*)(Wlast + 450);   // 152 (16B-aligned)
    float* ys  = hs + 152;                // 452
    float* xws = ys + 452;                // 452
    float* bhs = xws + 452;               // 452
    int b = blockIdx.x;
    int t = threadIdx.x;

    unsigned long long w2[KRP];
    if (t < 450) {
        const unsigned long long* wrow = (const unsigned long long*)(Wh + t*150);
        #pragma unroll
        for (int k = 0; k < KRP; k++) w2[k] = wrow[k];
        #pragma unroll
        for (int q = 0; q < WSV_N; q++) {
            ulonglong2 v;
            v.x = wrow[KRP + 2*q];
            v.y = wrow[KRP + 2*q + 1];
            WsV[q*450 + t] = v;
        }
        Wlast[t] = wrow[74];
        bhs[t] = __ldg(&bhv[t]);
    }
    if (t < 152) hs[t] = 0.f;
    __syncthreads();

    const float* xwb = Xw + (long long)b * 256 * 450;
    for (int step = 0; step < 256; step++) {
        if (t < 450) {
            float xw = xwb[step*450 + t];
            unsigned long long acc0 = 0, acc1 = 0;
            const ulonglong2* hp = (const ulonglong2*)hs;
            #pragma unroll
            for (int k = 0; k < KRP/2; k++) {
                ulonglong2 h2 = hp[k];
                ffma2(acc0, w2[2*k],     h2.x);
                ffma2(acc1, w2[2*k + 1], h2.y);
            }
            #pragma unroll
            for (int q = 0; q < WSV_N; q++) {
                ulonglong2 h2 = hp[KRP/2 + q];
                ulonglong2 wv = WsV[q*450 + t];
                ffma2(acc0, wv.x, h2.x);
                ffma2(acc1, wv.y, h2.y);
            }
            {
                unsigned long long hl = ((const unsigned long long*)hs)[74];
                ffma2(acc0, Wlast[t], hl);
            }
            float s = __uint_as_float((unsigned)acc0) + __uint_as_float((unsigned)(acc0 >> 32))
                    + __uint_as_float((unsigned)acc1) + __uint_as_float((unsigned)(acc1 >> 32));
            ys[t] = s + bhs[t];
            xws[t] = xw;
        }
        __syncthreads();
        if (t < 150) {
            float r = sigmf(xws[t]       + ys[t]);
            float z = sigmf(xws[150 + t] + ys[150 + t]);
            float n = tanhf_fast(xws[300 + t] + r * ys[300 + t]);
            float h = (1.f - z) * n + z * hs[t];
            hs[t] = h;
            if (seqout) seqout[((long long)b*256 + step)*150 + t] = h;
        }
        __syncthreads();
    }
    if (hend && t < 150) hend[b*150 + t] = hs[t];
}

// ---------------- predictions head ----------------
__global__ void pred_kernel(const float* __restrict__ hend,
                            const float* __restrict__ f0w, const float* __restrict__ f0b,
                            const float* __restrict__ f1w, const float* __restrict__ f1b,
                            float* __restrict__ out)
{
    __shared__ float he[152];
    __shared__ float t0[152];
    int b = blockIdx.x, tid = threadIdx.x;
    if (tid < 150) he[tid] = hend[b*150 + tid];
    __syncthreads();
    if (tid < 150) {
        float s = __ldg(&f0b[tid]);
        for (int k = 0; k < 150; k++) s += he[k] * __ldg(&f0w[k*150 + tid]);
        t0[tid] = fmaxf(s, 0.f);
    }
    __syncthreads();
    if (tid < 64) {
        float s = __ldg(&f1b[tid]);
        for (int k = 0; k < 150; k++) s += t0[k] * __ldg(&f1w[k*64 + tid]);
        out[b*64 + tid] = s;
    }
}

// ---------------- h_rep: h_rep.flat[b][r] = h_end[b][r >> 8] (repeat+reshape quirk) ----------------
__global__ void hrep_kernel(const float* __restrict__ hend, float* __restrict__ hrep) {
    int idx = blockIdx.x * 256 + threadIdx.x;
    if (idx < B_*WSZ*HD) {
        int b = idx / (WSZ*HD);
        int r = idx - b*(WSZ*HD);
        hrep[idx] = hend[b*HD + (r >> 8)];
    }
}

// ---------------- launch ----------------
extern "C" void kernel_launch(void* const* d_in, const int* in_sizes, int n_in,
                              void* d_out, int out_size)
{
    (void)in_sizes; (void)n_in; (void)out_size;
    const float* x      = (const float*)d_in[0];
    const float* conv_w = (const float*)d_in[1];
    const float* conv_b = (const float*)d_in[2];
    const float* fW     = (const float*)d_in[3];
    const float* fb     = (const float*)d_in[4];
    const float* fa     = (const float*)d_in[5];
    const float* fbias  = (const float*)d_in[6];
    const float* tW     = (const float*)d_in[7];
    const float* tb     = (const float*)d_in[8];
    const float* ta     = (const float*)d_in[9];
    const float* tbias  = (const float*)d_in[10];
    const float* gWi    = (const float*)d_in[11];
    const float* gWh    = (const float*)d_in[12];
    const float* gbi    = (const float*)d_in[13];
    const float* gbh    = (const float*)d_in[14];
    const float* f0w    = (const float*)d_in[15];
    const float* f0b    = (const float*)d_in[16];
    const float* f1w    = (const float*)d_in[17];
    const float* f1b    = (const float*)d_in[18];
    const float* rWi    = (const float*)d_in[19];
    const float* rWh    = (const float*)d_in[20];
    const float* rbi    = (const float*)d_in[21];
    const float* rbh    = (const float*)d_in[22];
    const float* rfw    = (const float*)d_in[23];
    const float* rfb    = (const float*)d_in[24];
    float* out = (float*)d_out;

    float *hcat, *g1f, *g2f, *g1t, *g2t, *xw, *hend, *hrep, *dec;
    cudaGetSymbolAddress((void**)&hcat, g_hcat);
    cudaGetSymbolAddress((void**)&g1f,  g_g1f);
    cudaGetSymbolAddress((void**)&g2f,  g_g2f);
    cudaGetSymbolAddress((void**)&g1t,  g_g1t);
    cudaGetSymbolAddress((void**)&g2t,  g_g2t);
    cudaGetSymbolAddress((void**)&xw,   g_xw);
    cudaGetSymbolAddress((void**)&hend, g_hend);
    cudaGetSymbolAddress((void**)&hrep, g_hrep);
    cudaGetSymbolAddress((void**)&dec,  g_dec);

    const int gru_smem = GRU_SMEM_BYTES;
    cudaFuncSetAttribute(gru_kernel, cudaFuncAttributeMaxDynamicSharedMemorySize, gru_smem);

    // 1. conv weight transpose + conv -> hcat[:, :, 0:64]
    prep_cwt_kernel<<<(KS_*64*64 + 255)/256, 256>>>(conv_w);
    conv_kernel<<<dim3(32, 16), 512>>>(x, conv_b);

    // 2+3. all four GAT projections in ONE launch (512 CTAs)
    proj4_kernel<<<512, 256>>>(fW, fb, tW, tb);

    // 4. attention e + softmax (both GATs)
    gat_e_feat_kernel<<<dim3(64, 16), 256>>>(g1f, g2f, fa, fbias);
    gat_e_temp_kernel<<<dim3(256, 16), 256>>>(g1t, g2t, ta, tbias);

    // 5. aggregation GEMMs with fused sigmoid -> hcat[64:128], hcat[128:192]
    gatagg_kernel<<<128, 256>>>();

    // 6. encoder xW = hcat @ gWi^T + gbi : [256,192]@[192,450]
    gemm_kernel<<<dim3(8, 4, 16), 256>>>(hcat, 192, 1, 256*192, gWi, 1, 192, gbi, xw, 256*450, 256, 450, 192);
    // 7. encoder GRU -> h_end
    gru_kernel<<<16, 480, gru_smem>>>(xw, gWh, gbh, hend, nullptr);
    // 8. predictions
    pred_kernel<<<16, 192>>>(hend, f0w, f0b, f1w, f1b, out);
    // 9. h_rep
    hrep_kernel<<<(B_*WSZ*HD + 255)/256, 256>>>(hend, hrep);
    // 10. decoder xW = h_rep @ rWi^T + rbi : [256,150]@[150,450]
    gemm_kernel<<<dim3(8, 4, 16), 256>>>(hrep, 150, 1, 256*150, rWi, 1, 150, rbi, xw, 256*450, 256, 450, 150);
    // 11. decoder GRU -> dec_out
    gru_kernel<<<16, 480, gru_smem>>>(xw, rWh, rbh, nullptr, dec);
    // 12. recons = dec_out @ rfw + rfb
    gemm_kernel<<<dim3(1, 4, 16), 256>>>(dec, 150, 1, 256*150, rfw, 64, 1, rfb, out + 1024, 256*64, 256, 64, 150);
}

// round 15
// speedup vs baseline: 1.2054x; 1.0564x over previous
#include <cuda_runtime.h>
#include <math.h>

#define B_   16
#define WSZ  256
#define KF   64
#define HD   150
#define KS_  7

// ---------------- scratch (device globals; no allocation allowed) ----------------
__device__ float g_hcat[B_*WSZ*192];      // [b, t, 0:64]=xc, [64:128]=h_feat, [128:192]=h_temp
__device__ float g_g1f[B_*64*512];
__device__ float g_g2f[B_*64*512];
__device__ float g_g1t[B_*256*128];
__device__ float g_g2t[B_*256*128];
__device__ float g_attf[B_*64*64];        // feature GAT attention rows
__device__ float g_attt[B_*256*256];      // temporal GAT attention rows
__device__ float g_xw[B_*256*450];        // reused by enc then dec
__device__ float g_hend[B_*HD];
__device__ float g_hrep[B_*WSZ*HD];
__device__ float g_dec[B_*WSZ*HD];
__device__ float g_cwt[KS_*64*64];        // conv_w transposed to [s][i][k]

__device__ __forceinline__ float sigmf(float x) {
    return __fdividef(1.f, 1.f + __expf(-x));
}
__device__ __forceinline__ float tanhf_fast(float x) {
    x = fminf(fmaxf(x, -30.f), 30.f);
    float e = __expf(2.f * x);
    return __fdividef(e - 1.f, e + 1.f);
}

// packed f32x2 fma: d += a*b (elementwise on 2 packed floats in b64 regs)
__device__ __forceinline__ void ffma2(unsigned long long& d, unsigned long long a, unsigned long long b) {
    asm("fma.rn.f32x2 %0, %1, %2, %3;" : "=l"(d) : "l"(a), "l"(b), "l"(d));
}

// ---------------- conv weight transpose ----------------
__global__ void prep_cwt_kernel(const float* __restrict__ cw) {
    int idx = blockIdx.x * 256 + threadIdx.x;
    if (idx < KS_*64*64) {
        int k = idx / 448;
        int r = idx - k*448;
        int i = r / 7;
        int s = r - i*7;
        g_cwt[(s*64 + i)*64 + k] = cw[idx];
    }
}

// ---------------- conv1d + bias + relu -> hcat cols [0:64] ----------------
__global__ void conv_kernel(const float* __restrict__ x, const float* __restrict__ cb) {
    __shared__ float xs[14*64];
    int b = blockIdx.y, w0 = blockIdx.x * 8;
    int tid = threadIdx.x;
    for (int idx = tid; idx < 14*64; idx += 512) {
        int row = idx >> 6, i = idx & 63;
        int wg = w0 + row - 3;
        xs[idx] = (wg >= 0 && wg < WSZ) ? x[(b*WSZ + wg)*64 + i] : 0.f;
    }
    __syncthreads();
    int wl = tid >> 6, k = tid & 63;
    float acc = __ldg(&cb[k]);
    #pragma unroll
    for (int s = 0; s < 7; s++) {
        const float* cwp = &g_cwt[(s*64)*64 + k];
        const float* xp  = &xs[(wl + s)*64];
        #pragma unroll
        for (int i = 0; i < 64; i++)
            acc += xp[i] * __ldg(&cwp[i*64]);
    }
    g_hcat[(b*WSZ + w0 + wl)*192 + k] = fmaxf(acc, 0.f);
}

// ---------------- shared GEMM body with strided/activated epilogue ----------------
__device__ __forceinline__ void gemm_body(const float* __restrict__ Ab, int a_rs, int a_cs,
                                          const float* __restrict__ Bm, int b_rs, int b_cs,
                                          const float* __restrict__ bias,
                                          float* __restrict__ Cb,
                                          int M, int N, int K, int m0, int n0,
                                          int c_rs, int c_cs, int act,
                                          float As[16][64], float Bs[16][64])
{
    int tid = threadIdx.x;
    int tx = tid & 15, ty = tid >> 4;
    float acc[4][4] = {};
    for (int k0 = 0; k0 < K; k0 += 16) {
        if (a_cs == 1) {
            #pragma unroll
            for (int l = 0; l < 4; l++) {
                int idx = tid + l*256;
                int mm = idx >> 4, kk = idx & 15;
                int m = m0 + mm, k = k0 + kk;
                As[kk][mm] = (m < M && k < K) ? Ab[m*a_rs + k] : 0.f;
            }
        } else {
            #pragma unroll
            for (int l = 0; l < 4; l++) {
                int idx = tid + l*256;
                int kk = idx >> 6, mm = idx & 63;
                int m = m0 + mm, k = k0 + kk;
                As[kk][mm] = (m < M && k < K) ? Ab[m*a_rs + k*a_cs] : 0.f;
            }
        }
        if (b_cs == 1) {
            #pragma unroll
            for (int l = 0; l < 4; l++) {
                int idx = tid + l*256;
                int kk = idx >> 6, nn = idx & 63;
                int n = n0 + nn, k = k0 + kk;
                Bs[kk][nn] = (n < N && k < K) ? Bm[k*b_rs + n] : 0.f;
            }
        } else {
            #pragma unroll
            for (int l = 0; l < 4; l++) {
                int idx = tid + l*256;
                int nn = idx >> 4, kk = idx & 15;
                int n = n0 + nn, k = k0 + kk;
                Bs[kk][nn] = (n < N && k < K) ? Bm[k*b_rs + n*b_cs] : 0.f;
            }
        }
        __syncthreads();
        #pragma unroll
        for (int kk = 0; kk < 16; kk++) {
            float4 av = *(const float4*)&As[kk][ty*4];
            float4 bv = *(const float4*)&Bs[kk][tx*4];
            float a_[4] = {av.x, av.y, av.z, av.w};
            float b_[4] = {bv.x, bv.y, bv.z, bv.w};
            #pragma unroll
            for (int i = 0; i < 4; i++)
                #pragma unroll
                for (int j = 0; j < 4; j++)
                    acc[i][j] += a_[i] * b_[j];
        }
        __syncthreads();
    }
    #pragma unroll
    for (int i = 0; i < 4; i++) {
        int m = m0 + ty*4 + i;
        if (m >= M) continue;
        #pragma unroll
        for (int j = 0; j < 4; j++) {
            int n = n0 + tx*4 + j;
            if (n >= N) continue;
            float v = acc[i][j] + (bias ? __ldg(&bias[n]) : 0.f);
            if (act) v = sigmf(v);
            Cb[m*c_rs + n*c_cs] = v;
        }
    }
}

__global__ void gemm_kernel(const float* __restrict__ A, int a_rs, int a_cs, int a_bs,
                            const float* __restrict__ Bm, int b_rs, int b_cs,
                            const float* __restrict__ bias,
                            float* __restrict__ C, int c_bs,
                            int M, int N, int K)
{
    __shared__ float As[16][64];
    __shared__ float Bs[16][64];
    gemm_body(A + (long long)blockIdx.z * a_bs, a_rs, a_cs, Bm, b_rs, b_cs, bias,
              C + (long long)blockIdx.z * c_bs, M, N, K, blockIdx.y*64, blockIdx.x*64,
              N, 1, 0, As, Bs);
}

// ---------------- fused 4-way projection GEMM (g1f,g2f,g1t,g2t in ONE launch) ----------------
__global__ void proj4_kernel(const float* __restrict__ fW, const float* __restrict__ fb,
                             const float* __restrict__ tW, const float* __restrict__ tb)
{
    __shared__ float As[16][64];
    __shared__ float Bs[16][64];
    int task = blockIdx.x >> 7;
    int bid  = blockIdx.x & 127;
    if (task < 2) {
        int bx = bid & 7, bz = bid >> 3;
        const float* Ab = g_hcat + bz*256*192;
        const float* Bm = (task == 0) ? fW : (fW + 256*512);
        const float* bias = (task == 0) ? nullptr : fb;
        float* Cb = ((task == 0) ? g_g1f : g_g2f) + bz*64*512;
        gemm_body(Ab, 1, 192, Bm, 512, 1, bias, Cb, 64, 512, 256, 0, bx*64, 512, 1, 0, As, Bs);
    } else {
        int bx = bid & 1, by = (bid >> 1) & 3, bz = bid >> 3;
        const float* Ab = g_hcat + bz*256*192;
        const float* Bm = (task == 2) ? tW : (tW + 64*128);
        const float* bias = (task == 2) ? nullptr : tb;
        float* Cb = ((task == 2) ? g_g1t : g_g2t) + bz*256*128;
        gemm_body(Ab, 192, 1, Bm, 128, 1, bias, Cb, 256, 128, 64, by*64, bx*64, 128, 1, 0, As, Bs);
    }
}

// ---------------- feature GAT e + softmax, SMEM-staged (4 CTAs/batch x 16 i) ----------------
// leaky(x) = 0.6x + 0.4|x| exactly (slope 0.2)
#define GF_SMEM ((64*513 + 16*512 + 512)*4)
__global__ void gat_e_feat2_kernel(const float* __restrict__ g1f, const float* __restrict__ g2f,
                                   const float* __restrict__ fa, const float* __restrict__ fbias)
{
    extern __shared__ float sm[];
    float* g2s = sm;                  // [64][513]
    float* g1s = sm + 64*513;         // [16][512]
    float* fas = g1s + 16*512;        // [512]
    int b = blockIdx.y, i0 = blockIdx.x * 16;
    int tid = threadIdx.x;            // 512
    int lane = tid & 31, warp = tid >> 5;

    for (int idx = tid; idx < 64*512; idx += 512) {
        int j = idx >> 9, e = idx & 511;
        g2s[j*513 + e] = g2f[(b*64 + j)*512 + e];
    }
    for (int idx = tid; idx < 16*512; idx += 512) {
        int ii = idx >> 9, e = idx & 511;
        g1s[idx] = g1f[(b*64 + i0 + ii)*512 + e];
    }
    fas[tid] = __ldg(&fa[tid]);
    __syncthreads();

    // warp = ii; lane handles j = lane and lane+32
    int i = i0 + warp;
    const float* g1p = &g1s[warp*512];
    float a1_0 = 0.f, a2_0 = 0.f, a1_1 = 0.f, a2_1 = 0.f;
    const float* g2p0 = &g2s[lane*513];
    const float* g2p1 = &g2s[(lane + 32)*513];
    for (int e = 0; e < 512; e++) {
        float g1v = g1p[e];
        float fv  = fas[e];
        float x0 = g1v + g2p0[e];
        float x1 = g1v + g2p1[e];
        a1_0 += fv * x0;  a2_0 += fv * fabsf(x0);
        a1_1 += fv * x1;  a2_1 += fv * fabsf(x1);
    }
    float e0 = 0.6f*a1_0 + 0.4f*a2_0 + __ldg(&fbias[i*64 + lane]);
    float e1 = 0.6f*a1_1 + 0.4f*a2_1 + __ldg(&fbias[i*64 + lane + 32]);
    float m = fmaxf(e0, e1);
    #pragma unroll
    for (int o = 16; o > 0; o >>= 1) m = fmaxf(m, __shfl_xor_sync(0xffffffffu, m, o));
    float p0 = __expf(e0 - m), p1 = __expf(e1 - m);
    float ss = p0 + p1;
    #pragma unroll
    for (int o = 16; o > 0; o >>= 1) ss += __shfl_xor_sync(0xffffffffu, ss, o);
    float inv = __fdividef(1.f, ss);
    g_attf[(b*64 + i)*64 + lane]      = p0 * inv;
    g_attf[(b*64 + i)*64 + lane + 32] = p1 * inv;
}

// ---------------- temporal GAT e + softmax, SMEM-staged (8 CTAs/batch x 32 i) ----------------
#define GT_SMEM ((256*129 + 32*128 + 128)*4)
__global__ void gat_e_temp2_kernel(const float* __restrict__ g1t, const float* __restrict__ g2t,
                                   const float* __restrict__ ta, const float* __restrict__ tbias)
{
    extern __shared__ float sm[];
    float* g2s = sm;                  // [256][129]
    float* g1s = sm + 256*129;        // [32][128]
    float* tas = g1s + 32*128;        // [128]
    int b = blockIdx.y, i0 = blockIdx.x * 32;
    int tid = threadIdx.x;            // 512

    for (int idx = tid; idx < 256*128; idx += 512) {
        int j = idx >> 7, e = idx & 127;
        g2s[j*129 + e] = g2t[(b*WSZ + j)*128 + e];
    }
    for (int idx = tid; idx < 32*128; idx += 512) {
        g1s[idx] = g1t[(b*WSZ + i0 + (idx >> 7))*128 + (idx & 127)];
    }
    if (tid < 128) tas[tid] = __ldg(&ta[tid]);
    __syncthreads();

    int ii = tid >> 4;        // 0..31
    int jt = tid & 15;        // 0..15 ; this thread owns j = jt + 16k
    int i = i0 + ii;
    const float* g1p = &g1s[ii*128];
    float acc1[16], acc2[16];
    #pragma unroll
    for (int k = 0; k < 16; k++) { acc1[k] = 0.f; acc2[k] = 0.f; }
    for (int e = 0; e < 128; e++) {
        float g1v = g1p[e];
        float tv  = tas[e];
        const float* g2e = &g2s[jt*129 + e];
        #pragma unroll
        for (int k = 0; k < 16; k++) {
            float x = g1v + g2e[k*16*129];
            acc1[k] += tv * x;
            acc2[k] += tv * fabsf(x);
        }
    }
    float es[16];
    float mx = -1e30f;
    #pragma unroll
    for (int k = 0; k < 16; k++) {
        es[k] = 0.6f*acc1[k] + 0.4f*acc2[k] + __ldg(&tbias[i*256 + jt + k*16]);
        mx = fmaxf(mx, es[k]);
    }
    #pragma unroll
    for (int o = 8; o > 0; o >>= 1) mx = fmaxf(mx, __shfl_xor_sync(0xffffffffu, mx, o));
    float sum = 0.f;
    #pragma unroll
    for (int k = 0; k < 16; k++) { es[k] = __expf(es[k] - mx); sum += es[k]; }
    #pragma unroll
    for (int o = 8; o > 0; o >>= 1) sum += __shfl_xor_sync(0xffffffffu, sum, o);
    float inv = __fdividef(1.f, sum);
    #pragma unroll
    for (int k = 0; k < 16; k++)
        g_attt[(b*WSZ + i)*256 + jt + k*16] = es[k] * inv;
}

// ---------------- fused GAT aggregation GEMMs (feature + temporal, one launch) ----------------
__global__ void gatagg_kernel()
{
    __shared__ float As[16][64];
    __shared__ float Bs[16][64];
    int bid = blockIdx.x;
    if (bid < 64) {
        int b = bid >> 2, fx = bid & 3;
        gemm_body(g_attf + b*64*64, 64, 1,
                  g_hcat + b*WSZ*192, 1, 192, nullptr,
                  g_hcat + b*WSZ*192 + 64,
                  64, 256, 64, 0, fx*64, 1, 192, 1, As, Bs);
    } else {
        int bid2 = bid - 64;
        int b = bid2 >> 2, my = bid2 & 3;
        gemm_body(g_attt + b*256*256, 256, 1,
                  g_hcat + b*WSZ*192, 192, 1, nullptr,
                  g_hcat + b*WSZ*192 + 128,
                  256, 64, 256, my*64, 0, 192, 1, 1, As, Bs);
    }
}

// ---------------- persistent GRU, f32x2 packed + xw prefetch pipelining ----------------
#define KRP 48            // reg pairs
#define WSV_N 13          // smem ulonglong2 entries per thread (26 pairs)
#define GRU_SMEM_BYTES (WSV_N*450*16 + 450*8 + (152 + 452 + 452 + 452)*4)

__global__ __launch_bounds__(480, 1)
void gru_kernel(const float* __restrict__ Xw,     // [B,256,450] (includes bi)
                const float* __restrict__ Wh,     // [450,150]
                const float* __restrict__ bhv,    // [450]
                float* __restrict__ hend,         // [B,150] or null
                float* __restrict__ seqout)       // [B,256,150] or null
{
    extern __shared__ float sm[];
    ulonglong2* WsV = (ulonglong2*)sm;                                  // [WSV_N][450]
    unsigned long long* Wlast = (unsigned long long*)(WsV + WSV_N*450); // [450]
    float* hs  = (float*)(Wlast + 450);   // 152 (16B-aligned)
    float* ys  = hs + 152;                // 452
    float* xws = ys + 452;                // 452
    float* bhs = xws + 452;               // 452
    int b = blockIdx.x;
    int t = threadIdx.x;

    unsigned long long w2[KRP];
    if (t < 450) {
        const unsigned long long* wrow = (const unsigned long long*)(Wh + t*150);
        #pragma unroll
        for (int k = 0; k < KRP; k++) w2[k] = wrow[k];
        #pragma unroll
        for (int q = 0; q < WSV_N; q++) {
            ulonglong2 v;
            v.x = wrow[KRP + 2*q];
            v.y = wrow[KRP + 2*q + 1];
            WsV[q*450 + t] = v;
        }
        Wlast[t] = wrow[74];
        bhs[t] = __ldg(&bhv[t]);
    }
    if (t < 152) hs[t] = 0.f;
    __syncthreads();

    const float* xwb = Xw + (long long)b * 256 * 450;
    float xw_cur = (t < 450) ? xwb[t] : 0.f;     // prefetched step 0
    for (int step = 0; step < 256; step++) {
        if (t < 450) {
            // issue next step's load FIRST so its latency hides under this step's FMA chain
            float xw_next = (step + 1 < 256) ? xwb[(step + 1)*450 + t] : 0.f;
            unsigned long long acc0 = 0, acc1 = 0;
            const ulonglong2* hp = (const ulonglong2*)hs;
            #pragma unroll
            for (int k = 0; k < KRP/2; k++) {
                ulonglong2 h2 = hp[k];
                ffma2(acc0, w2[2*k],     h2.x);
                ffma2(acc1, w2[2*k + 1], h2.y);
            }
            #pragma unroll
            for (int q = 0; q < WSV_N; q++) {
                ulonglong2 h2 = hp[KRP/2 + q];
                ulonglong2 wv = WsV[q*450 + t];
                ffma2(acc0, wv.x, h2.x);
                ffma2(acc1, wv.y, h2.y);
            }
            {
                unsigned long long hl = ((const unsigned long long*)hs)[74];
                ffma2(acc0, Wlast[t], hl);
            }
            float s = __uint_as_float((unsigned)acc0) + __uint_as_float((unsigned)(acc0 >> 32))
                    + __uint_as_float((unsigned)acc1) + __uint_as_float((unsigned)(acc1 >> 32));
            ys[t] = s + bhs[t];
            xws[t] = xw_cur;
            xw_cur = xw_next;
        }
        __syncthreads();
        if (t < 150) {
            float r = sigmf(xws[t]       + ys[t]);
            float z = sigmf(xws[150 + t] + ys[150 + t]);
            float n = tanhf_fast(xws[300 + t] + r * ys[300 + t]);
            float h = (1.f - z) * n + z * hs[t];
            hs[t] = h;
            if (seqout) seqout[((long long)b*256 + step)*150 + t] = h;
        }
        __syncthreads();
    }
    if (hend && t < 150) hend[b*150 + t] = hs[t];
}

// ---------------- predictions head ----------------
__global__ void pred_kernel(const float* __restrict__ hend,
                            const float* __restrict__ f0w, const float* __restrict__ f0b,
                            const float* __restrict__ f1w, const float* __restrict__ f1b,
                            float* __restrict__ out)
{
    __shared__ float he[152];
    __shared__ float t0[152];
    int b = blockIdx.x, tid = threadIdx.x;
    if (tid < 150) he[tid] = hend[b*150 + tid];
    __syncthreads();
    if (tid < 150) {
        float s = __ldg(&f0b[tid]);
        for (int k = 0; k < 150; k++) s += he[k] * __ldg(&f0w[k*150 + tid]);
        t0[tid] = fmaxf(s, 0.f);
    }
    __syncthreads();
    if (tid < 64) {
        float s = __ldg(&f1b[tid]);
        for (int k = 0; k < 150; k++) s += t0[k] * __ldg(&f1w[k*64 + tid]);
        out[b*64 + tid] = s;
    }
}

// ---------------- h_rep: h_rep.flat[b][r] = h_end[b][r >> 8] (repeat+reshape quirk) ----------------
__global__ void hrep_kernel(const float* __restrict__ hend, float* __restrict__ hrep) {
    int idx = blockIdx.x * 256 + threadIdx.x;
    if (idx < B_*WSZ*HD) {
        int b = idx / (WSZ*HD);
        int r = idx - b*(WSZ*HD);
        hrep[idx] = hend[b*HD + (r >> 8)];
    }
}

// ---------------- launch ----------------
extern "C" void kernel_launch(void* const* d_in, const int* in_sizes, int n_in,
                              void* d_out, int out_size)
{
    (void)in_sizes; (void)n_in; (void)out_size;
    const float* x      = (const float*)d_in[0];
    const float* conv_w = (const float*)d_in[1];
    const float* conv_b = (const float*)d_in[2];
    const float* fW     = (const float*)d_in[3];
    const float* fb     = (const float*)d_in[4];
    const float* fa     = (const float*)d_in[5];
    const float* fbias  = (const float*)d_in[6];
    const float* tW     = (const float*)d_in[7];
    const float* tb     = (const float*)d_in[8];
    const float* ta     = (const float*)d_in[9];
    const float* tbias  = (const float*)d_in[10];
    const float* gWi    = (const float*)d_in[11];
    const float* gWh    = (const float*)d_in[12];
    const float* gbi    = (const float*)d_in[13];
    const float* gbh    = (const float*)d_in[14];
    const float* f0w    = (const float*)d_in[15];
    const float* f0b    = (const float*)d_in[16];
    const float* f1w    = (const float*)d_in[17];
    const float* f1b    = (const float*)d_in[18];
    const float* rWi    = (const float*)d_in[19];
    const float* rWh    = (const float*)d_in[20];
    const float* rbi    = (const float*)d_in[21];
    const float* rbh    = (const float*)d_in[22];
    const float* rfw    = (const float*)d_in[23];
    const float* rfb    = (const float*)d_in[24];
    float* out = (float*)d_out;

    float *hcat, *g1f, *g2f, *g1t, *g2t, *xw, *hend, *hrep, *dec;
    cudaGetSymbolAddress((void**)&hcat, g_hcat);
    cudaGetSymbolAddress((void**)&g1f,  g_g1f);
    cudaGetSymbolAddress((void**)&g2f,  g_g2f);
    cudaGetSymbolAddress((void**)&g1t,  g_g1t);
    cudaGetSymbolAddress((void**)&g2t,  g_g2t);
    cudaGetSymbolAddress((void**)&xw,   g_xw);
    cudaGetSymbolAddress((void**)&hend, g_hend);
    cudaGetSymbolAddress((void**)&hrep, g_hrep);
    cudaGetSymbolAddress((void**)&dec,  g_dec);

    const int gru_smem = GRU_SMEM_BYTES;
    cudaFuncSetAttribute(gru_kernel, cudaFuncAttributeMaxDynamicSharedMemorySize, gru_smem);
    cudaFuncSetAttribute(gat_e_feat2_kernel, cudaFuncAttributeMaxDynamicSharedMemorySize, GF_SMEM);
    cudaFuncSetAttribute(gat_e_temp2_kernel, cudaFuncAttributeMaxDynamicSharedMemorySize, GT_SMEM);

    // 1. conv weight transpose + conv -> hcat[:, :, 0:64]
    prep_cwt_kernel<<<(KS_*64*64 + 255)/256, 256>>>(conv_w);
    conv_kernel<<<dim3(32, 16), 512>>>(x, conv_b);

    // 2+3. all four GAT projections in ONE launch (512 CTAs)
    proj4_kernel<<<512, 256>>>(fW, fb, tW, tb);

    // 4. attention e + softmax (SMEM-staged, L2-traffic-free)
    gat_e_feat2_kernel<<<dim3(4, 16), 512, GF_SMEM>>>(g1f, g2f, fa, fbias);
    gat_e_temp2_kernel<<<dim3(8, 16), 512, GT_SMEM>>>(g1t, g2t, ta, tbias);

    // 5. aggregation GEMMs with fused sigmoid -> hcat[64:128], hcat[128:192]
    gatagg_kernel<<<128, 256>>>();

    // 6. encoder xW = hcat @ gWi^T + gbi : [256,192]@[192,450]
    gemm_kernel<<<dim3(8, 4, 16), 256>>>(hcat, 192, 1, 256*192, gWi, 1, 192, gbi, xw, 256*450, 256, 450, 192);
    // 7. encoder GRU -> h_end
    gru_kernel<<<16, 480, gru_smem>>>(xw, gWh, gbh, hend, nullptr);
    // 8. predictions
    pred_kernel<<<16, 192>>>(hend, f0w, f0b, f1w, f1b, out);
    // 9. h_rep
    hrep_kernel<<<(B_*WSZ*HD + 255)/256, 256>>>(hend, hrep);
    // 10. decoder xW = h_rep @ rWi^T + rbi : [256,150]@[150,450]
    gemm_kernel<<<dim3(8, 4, 16), 256>>>(hrep, 150, 1, 256*150, rWi, 1, 150, rbi, xw, 256*450, 256, 450, 150);
    // 11. decoder GRU -> dec_out
    gru_kernel<<<16, 480, gru_smem>>>(xw, rWh, rbh, nullptr, dec);
    // 12. recons = dec_out @ rfw + rfb
    gemm_kernel<<<dim3(1, 4, 16), 256>>>(dec, 150, 1, 256*150, rfw, 64, 1, rfb, out + 1024, 256*64, 256, 64, 150);
}

// round 16
// speedup vs baseline: 1.2127x; 1.0061x over previous
#include <cuda_runtime.h>
#include <math.h>

#define B_   16
#define WSZ  256
#define KF   64
#define HD   150
#define KS_  7

// ---------------- scratch (device globals; no allocation allowed) ----------------
__device__ float g_hcat[B_*WSZ*192];      // [b, t, 0:64]=xc, [64:128]=h_feat, [128:192]=h_temp
__device__ float g_g1f[B_*64*512];
__device__ float g_g2f[B_*64*512];
__device__ float g_g1t[B_*256*128];
__device__ float g_g2t[B_*256*128];
__device__ float g_attf[B_*64*64];        // feature GAT attention rows
__device__ float g_attt[B_*256*256];      // temporal GAT attention rows
__device__ float g_xw[B_*256*450];        // reused by enc then dec
__device__ float g_hend[B_*HD];
__device__ float g_hrep[B_*WSZ*HD];
__device__ float g_dec[B_*WSZ*HD];
__device__ float g_cwt[KS_*64*64];        // conv_w transposed to [s][i][k]

__device__ __forceinline__ float sigmf(float x) {
    return __fdividef(1.f, 1.f + __expf(-x));
}
__device__ __forceinline__ float tanhf_fast(float x) {
    x = fminf(fmaxf(x, -30.f), 30.f);
    float e = __expf(2.f * x);
    return __fdividef(e - 1.f, e + 1.f);
}

// packed f32x2 fma: d += a*b (elementwise on 2 packed floats in b64 regs)
__device__ __forceinline__ void ffma2(unsigned long long& d, unsigned long long a, unsigned long long b) {
    asm("fma.rn.f32x2 %0, %1, %2, %3;" : "=l"(d) : "l"(a), "l"(b), "l"(d));
}

// ---------------- conv weight transpose ----------------
__global__ void prep_cwt_kernel(const float* __restrict__ cw) {
    int idx = blockIdx.x * 256 + threadIdx.x;
    if (idx < KS_*64*64) {
        int k = idx / 448;
        int r = idx - k*448;
        int i = r / 7;
        int s = r - i*7;
        g_cwt[(s*64 + i)*64 + k] = cw[idx];
    }
}

// ---------------- conv1d + bias + relu -> hcat cols [0:64] ----------------
__global__ void conv_kernel(const float* __restrict__ x, const float* __restrict__ cb) {
    __shared__ float xs[14*64];
    int b = blockIdx.y, w0 = blockIdx.x * 8;
    int tid = threadIdx.x;
    for (int idx = tid; idx < 14*64; idx += 512) {
        int row = idx >> 6, i = idx & 63;
        int wg = w0 + row - 3;
        xs[idx] = (wg >= 0 && wg < WSZ) ? x[(b*WSZ + wg)*64 + i] : 0.f;
    }
    __syncthreads();
    int wl = tid >> 6, k = tid & 63;
    float acc = __ldg(&cb[k]);
    #pragma unroll
    for (int s = 0; s < 7; s++) {
        const float* cwp = &g_cwt[(s*64)*64 + k];
        const float* xp  = &xs[(wl + s)*64];
        #pragma unroll
        for (int i = 0; i < 64; i++)
            acc += xp[i] * __ldg(&cwp[i*64]);
    }
    g_hcat[(b*WSZ + w0 + wl)*192 + k] = fmaxf(acc, 0.f);
}

// ---------------- shared GEMM body with strided/activated epilogue ----------------
__device__ __forceinline__ void gemm_body(const float* __restrict__ Ab, int a_rs, int a_cs,
                                          const float* __restrict__ Bm, int b_rs, int b_cs,
                                          const float* __restrict__ bias,
                                          float* __restrict__ Cb,
                                          int M, int N, int K, int m0, int n0,
                                          int c_rs, int c_cs, int act,
                                          float As[16][64], float Bs[16][64])
{
    int tid = threadIdx.x;
    int tx = tid & 15, ty = tid >> 4;
    float acc[4][4] = {};
    for (int k0 = 0; k0 < K; k0 += 16) {
        if (a_cs == 1) {
            #pragma unroll
            for (int l = 0; l < 4; l++) {
                int idx = tid + l*256;
                int mm = idx >> 4, kk = idx & 15;
                int m = m0 + mm, k = k0 + kk;
                As[kk][mm] = (m < M && k < K) ? Ab[m*a_rs + k] : 0.f;
            }
        } else {
            #pragma unroll
            for (int l = 0; l < 4; l++) {
                int idx = tid + l*256;
                int kk = idx >> 6, mm = idx & 63;
                int m = m0 + mm, k = k0 + kk;
                As[kk][mm] = (m < M && k < K) ? Ab[m*a_rs + k*a_cs] : 0.f;
            }
        }
        if (b_cs == 1) {
            #pragma unroll
            for (int l = 0; l < 4; l++) {
                int idx = tid + l*256;
                int kk = idx >> 6, nn = idx & 63;
                int n = n0 + nn, k = k0 + kk;
                Bs[kk][nn] = (n < N && k < K) ? Bm[k*b_rs + n] : 0.f;
            }
        } else {
            #pragma unroll
            for (int l = 0; l < 4; l++) {
                int idx = tid + l*256;
                int nn = idx >> 4, kk = idx & 15;
                int n = n0 + nn, k = k0 + kk;
                Bs[kk][nn] = (n < N && k < K) ? Bm[k*b_rs + n*b_cs] : 0.f;
            }
        }
        __syncthreads();
        #pragma unroll
        for (int kk = 0; kk < 16; kk++) {
            float4 av = *(const float4*)&As[kk][ty*4];
            float4 bv = *(const float4*)&Bs[kk][tx*4];
            float a_[4] = {av.x, av.y, av.z, av.w};
            float b_[4] = {bv.x, bv.y, bv.z, bv.w};
            #pragma unroll
            for (int i = 0; i < 4; i++)
                #pragma unroll
                for (int j = 0; j < 4; j++)
                    acc[i][j] += a_[i] * b_[j];
        }
        __syncthreads();
    }
    #pragma unroll
    for (int i = 0; i < 4; i++) {
        int m = m0 + ty*4 + i;
        if (m >= M) continue;
        #pragma unroll
        for (int j = 0; j < 4; j++) {
            int n = n0 + tx*4 + j;
            if (n >= N) continue;
            float v = acc[i][j] + (bias ? __ldg(&bias[n]) : 0.f);
            if (act) v = sigmf(v);
            Cb[m*c_rs + n*c_cs] = v;
        }
    }
}

__global__ void gemm_kernel(const float* __restrict__ A, int a_rs, int a_cs, int a_bs,
                            const float* __restrict__ Bm, int b_rs, int b_cs,
                            const float* __restrict__ bias,
                            float* __restrict__ C, int c_bs,
                            int M, int N, int K)
{
    __shared__ float As[16][64];
    __shared__ float Bs[16][64];
    gemm_body(A + (long long)blockIdx.z * a_bs, a_rs, a_cs, Bm, b_rs, b_cs, bias,
              C + (long long)blockIdx.z * c_bs, M, N, K, blockIdx.y*64, blockIdx.x*64,
              N, 1, 0, As, Bs);
}

// ---------------- fused 4-way projection GEMM (g1f,g2f,g1t,g2t in ONE launch) ----------------
__global__ void proj4_kernel(const float* __restrict__ fW, const float* __restrict__ fb,
                             const float* __restrict__ tW, const float* __restrict__ tb)
{
    __shared__ float As[16][64];
    __shared__ float Bs[16][64];
    int task = blockIdx.x >> 7;
    int bid  = blockIdx.x & 127;
    if (task < 2) {
        int bx = bid & 7, bz = bid >> 3;
        const float* Ab = g_hcat + bz*256*192;
        const float* Bm = (task == 0) ? fW : (fW + 256*512);
        const float* bias = (task == 0) ? nullptr : fb;
        float* Cb = ((task == 0) ? g_g1f : g_g2f) + bz*64*512;
        gemm_body(Ab, 1, 192, Bm, 512, 1, bias, Cb, 64, 512, 256, 0, bx*64, 512, 1, 0, As, Bs);
    } else {
        int bx = bid & 1, by = (bid >> 1) & 3, bz = bid >> 3;
        const float* Ab = g_hcat + bz*256*192;
        const float* Bm = (task == 2) ? tW : (tW + 64*128);
        const float* bias = (task == 2) ? nullptr : tb;
        float* Cb = ((task == 2) ? g_g1t : g_g2t) + bz*256*128;
        gemm_body(Ab, 192, 1, Bm, 128, 1, bias, Cb, 256, 128, 64, by*64, bx*64, 128, 1, 0, As, Bs);
    }
}

// ---------------- feature GAT e + softmax v3: 8 i per CTA, 128 CTAs, thread=(i_local,j) ----------------
// leaky(x) = 0.6x + 0.4|x| exactly (slope 0.2)
#define GF_SMEM ((64*513 + 8*512 + 512 + 32)*4)
__global__ void gat_e_feat2_kernel(const float* __restrict__ g1f, const float* __restrict__ g2f,
                                   const float* __restrict__ fa, const float* __restrict__ fbias)
{
    extern __shared__ float sm[];
    float* g2s = sm;                  // [64][513]
    float* g1s = sm + 64*513;         // [8][512]
    float* fas = g1s + 8*512;         // [512]
    float* red = fas + 512;           // [32] cross-warp scratch (16 used)
    int b = blockIdx.y, i0 = blockIdx.x * 8;
    int tid = threadIdx.x;            // 512
    int lane = tid & 31, warp = tid >> 5;

    for (int idx = tid; idx < 64*512; idx += 512) {
        int j = idx >> 9, e = idx & 511;
        g2s[j*513 + e] = g2f[(b*64 + j)*512 + e];
    }
    for (int idx = tid; idx < 8*512; idx += 512) {
        int ii = idx >> 9, e = idx & 511;
        g1s[idx] = g1f[(b*64 + i0 + ii)*512 + e];
    }
    fas[tid] = __ldg(&fa[tid]);
    __syncthreads();

    int il = tid >> 6;                // 0..7 (warp-pair uniform)
    int j  = tid & 63;                // 0..63
    int i = i0 + il;
    const float* g1p = &g1s[il*512];
    const float* g2p = &g2s[j*513];
    float a1 = 0.f, a2 = 0.f;
    for (int e = 0; e < 512; e++) {
        float x = g1p[e] + g2p[e];
        float fv = fas[e];
        a1 += fv * x;
        a2 += fv * fabsf(x);
    }
    float ev = 0.6f*a1 + 0.4f*a2 + __ldg(&fbias[i*64 + j]);

    // softmax over j (spans 2 warps): warp shfl reduce then smem combine
    float m = ev;
    #pragma unroll
    for (int o = 16; o > 0; o >>= 1) m = fmaxf(m, __shfl_xor_sync(0xffffffffu, m, o));
    if (lane == 0) red[warp] = m;
    __syncthreads();
    float bm = fmaxf(red[il*2], red[il*2 + 1]);
    float p = __expf(ev - bm);
    float s = p;
    #pragma unroll
    for (int o = 16; o > 0; o >>= 1) s += __shfl_xor_sync(0xffffffffu, s, o);
    __syncthreads();                  // red reuse hazard
    if (lane == 0) red[warp] = s;
    __syncthreads();
    float tot = red[il*2] + red[il*2 + 1];
    g_attf[(b*64 + i)*64 + j] = __fdividef(p, tot);
}

// ---------------- temporal GAT e + softmax, SMEM-staged (8 CTAs/batch x 32 i) ----------------
#define GT_SMEM ((256*129 + 32*128 + 128)*4)
__global__ void gat_e_temp2_kernel(const float* __restrict__ g1t, const float* __restrict__ g2t,
                                   const float* __restrict__ ta, const float* __restrict__ tbias)
{
    extern __shared__ float sm[];
    float* g2s = sm;                  // [256][129]
    float* g1s = sm + 256*129;        // [32][128]
    float* tas = g1s + 32*128;        // [128]
    int b = blockIdx.y, i0 = blockIdx.x * 32;
    int tid = threadIdx.x;            // 512

    for (int idx = tid; idx < 256*128; idx += 512) {
        int j = idx >> 7, e = idx & 127;
        g2s[j*129 + e] = g2t[(b*WSZ + j)*128 + e];
    }
    for (int idx = tid; idx < 32*128; idx += 512) {
        g1s[idx] = g1t[(b*WSZ + i0 + (idx >> 7))*128 + (idx & 127)];
    }
    if (tid < 128) tas[tid] = __ldg(&ta[tid]);
    __syncthreads();

    int ii = tid >> 4;        // 0..31
    int jt = tid & 15;        // 0..15 ; this thread owns j = jt + 16k
    int i = i0 + ii;
    const float* g1p = &g1s[ii*128];
    float acc1[16], acc2[16];
    #pragma unroll
    for (int k = 0; k < 16; k++) { acc1[k] = 0.f; acc2[k] = 0.f; }
    for (int e = 0; e < 128; e++) {
        float g1v = g1p[e];
        float tv  = tas[e];
        const float* g2e = &g2s[jt*129 + e];
        #pragma unroll
        for (int k = 0; k < 16; k++) {
            float x = g1v + g2e[k*16*129];
            acc1[k] += tv * x;
            acc2[k] += tv * fabsf(x);
        }
    }
    float es[16];
    float mx = -1e30f;
    #pragma unroll
    for (int k = 0; k < 16; k++) {
        es[k] = 0.6f*acc1[k] + 0.4f*acc2[k] + __ldg(&tbias[i*256 + jt + k*16]);
        mx = fmaxf(mx, es[k]);
    }
    #pragma unroll
    for (int o = 8; o > 0; o >>= 1) mx = fmaxf(mx, __shfl_xor_sync(0xffffffffu, mx, o));
    float sum = 0.f;
    #pragma unroll
    for (int k = 0; k < 16; k++) { es[k] = __expf(es[k] - mx); sum += es[k]; }
    #pragma unroll
    for (int o = 8; o > 0; o >>= 1) sum += __shfl_xor_sync(0xffffffffu, sum, o);
    float inv = __fdividef(1.f, sum);
    #pragma unroll
    for (int k = 0; k < 16; k++)
        g_attt[(b*WSZ + i)*256 + jt + k*16] = es[k] * inv;
}

// ---------------- fused GAT aggregation GEMMs (feature + temporal, one launch) ----------------
__global__ void gatagg_kernel()
{
    __shared__ float As[16][64];
    __shared__ float Bs[16][64];
    int bid = blockIdx.x;
    if (bid < 64) {
        int b = bid >> 2, fx = bid & 3;
        gemm_body(g_attf + b*64*64, 64, 1,
                  g_hcat + b*WSZ*192, 1, 192, nullptr,
                  g_hcat + b*WSZ*192 + 64,
                  64, 256, 64, 0, fx*64, 1, 192, 1, As, Bs);
    } else {
        int bid2 = bid - 64;
        int b = bid2 >> 2, my = bid2 & 3;
        gemm_body(g_attt + b*256*256, 256, 1,
                  g_hcat + b*WSZ*192, 192, 1, nullptr,
                  g_hcat + b*WSZ*192 + 128,
                  256, 64, 256, my*64, 0, 192, 1, 1, As, Bs);
    }
}

// ---------------- persistent GRU, f32x2 packed + xw prefetch pipelining ----------------
#define KRP 48            // reg pairs
#define WSV_N 13          // smem ulonglong2 entries per thread (26 pairs)
#define GRU_SMEM_BYTES (WSV_N*450*16 + 450*8 + (152 + 452 + 452 + 452)*4)

__global__ __launch_bounds__(480, 1)
void gru_kernel(const float* __restrict__ Xw,     // [B,256,450] (includes bi)
                const float* __restrict__ Wh,     // [450,150]
                const float* __restrict__ bhv,    // [450]
                float* __restrict__ hend,         // [B,150] or null
                float* __restrict__ seqout)       // [B,256,150] or null
{
    extern __shared__ float sm[];
    ulonglong2* WsV = (ulonglong2*)sm;                                  // [WSV_N][450]
    unsigned long long* Wlast = (unsigned long long*)(WsV + WSV_N*450); // [450]
    float* hs  = (float*)(Wlast + 450);   // 152 (16B-aligned)
    float* ys  = hs + 152;                // 452
    float* xws = ys + 452;                // 452
    float* bhs = xws + 452;               // 452
    int b = blockIdx.x;
    int t = threadIdx.x;

    unsigned long long w2[KRP];
    if (t < 450) {
        const unsigned long long* wrow = (const unsigned long long*)(Wh + t*150);
        #pragma unroll
        for (int k = 0; k < KRP; k++) w2[k] = wrow[k];
        #pragma unroll
        for (int q = 0; q < WSV_N; q++) {
            ulonglong2 v;
            v.x = wrow[KRP + 2*q];
            v.y = wrow[KRP + 2*q + 1];
            WsV[q*450 + t] = v;
        }
        Wlast[t] = wrow[74];
        bhs[t] = __ldg(&bhv[t]);
    }
    if (t < 152) hs[t] = 0.f;
    __syncthreads();

    const float* xwb = Xw + (long long)b * 256 * 450;
    float xw_cur = (t < 450) ? xwb[t] : 0.f;     // prefetched step 0
    for (int step = 0; step < 256; step++) {
        if (t < 450) {
            // issue next step's load FIRST so its latency hides under this step's FMA chain
            float xw_next = (step + 1 < 256) ? xwb[(step + 1)*450 + t] : 0.f;
            unsigned long long acc0 = 0, acc1 = 0;
            const ulonglong2* hp = (const ulonglong2*)hs;
            #pragma unroll
            for (int k = 0; k < KRP/2; k++) {
                ulonglong2 h2 = hp[k];
                ffma2(acc0, w2[2*k],     h2.x);
                ffma2(acc1, w2[2*k + 1], h2.y);
            }
            #pragma unroll
            for (int q = 0; q < WSV_N; q++) {
                ulonglong2 h2 = hp[KRP/2 + q];
                ulonglong2 wv = WsV[q*450 + t];
                ffma2(acc0, wv.x, h2.x);
                ffma2(acc1, wv.y, h2.y);
            }
            {
                unsigned long long hl = ((const unsigned long long*)hs)[74];
                ffma2(acc0, Wlast[t], hl);
            }
            float s = __uint_as_float((unsigned)acc0) + __uint_as_float((unsigned)(acc0 >> 32))
                    + __uint_as_float((unsigned)acc1) + __uint_as_float((unsigned)(acc1 >> 32));
            ys[t] = s + bhs[t];
            xws[t] = xw_cur;
            xw_cur = xw_next;
        }
        __syncthreads();
        if (t < 150) {
            float r = sigmf(xws[t]       + ys[t]);
            float z = sigmf(xws[150 + t] + ys[150 + t]);
            float n = tanhf_fast(xws[300 + t] + r * ys[300 + t]);
            float h = (1.f - z) * n + z * hs[t];
            hs[t] = h;
            if (seqout) seqout[((long long)b*256 + step)*150 + t] = h;
        }
        __syncthreads();
    }
    if (hend && t < 150) hend[b*150 + t] = hs[t];
}

// ---------------- predictions head ----------------
__global__ void pred_kernel(const float* __restrict__ hend,
                            const float* __restrict__ f0w, const float* __restrict__ f0b,
                            const float* __restrict__ f1w, const float* __restrict__ f1b,
                            float* __restrict__ out)
{
    __shared__ float he[152];
    __shared__ float t0[152];
    int b = blockIdx.x, tid = threadIdx.x;
    if (tid < 150) he[tid] = hend[b*150 + tid];
    __syncthreads();
    if (tid < 150) {
        float s = __ldg(&f0b[tid]);
        for (int k = 0; k < 150; k++) s += he[k] * __ldg(&f0w[k*150 + tid]);
        t0[tid] = fmaxf(s, 0.f);
    }
    __syncthreads();
    if (tid < 64) {
        float s = __ldg(&f1b[tid]);
        for (int k = 0; k < 150; k++) s += t0[k] * __ldg(&f1w[k*64 + tid]);
        out[b*64 + tid] = s;
    }
}

// ---------------- h_rep: h_rep.flat[b][r] = h_end[b][r >> 8] (repeat+reshape quirk) ----------------
__global__ void hrep_kernel(const float* __restrict__ hend, float* __restrict__ hrep) {
    int idx = blockIdx.x * 256 + threadIdx.x;
    if (idx < B_*WSZ*HD) {
        int b = idx / (WSZ*HD);
        int r = idx - b*(WSZ*HD);
        hrep[idx] = hend[b*HD + (r >> 8)];
    }
}

// ---------------- launch ----------------
extern "C" void kernel_launch(void* const* d_in, const int* in_sizes, int n_in,
                              void* d_out, int out_size)
{
    (void)in_sizes; (void)n_in; (void)out_size;
    const float* x      = (const float*)d_in[0];
    const float* conv_w = (const float*)d_in[1];
    const float* conv_b = (const float*)d_in[2];
    const float* fW     = (const float*)d_in[3];
    const float* fb     = (const float*)d_in[4];
    const float* fa     = (const float*)d_in[5];
    const float* fbias  = (const float*)d_in[6];
    const float* tW     = (const float*)d_in[7];
    const float* tb     = (const float*)d_in[8];
    const float* ta     = (const float*)d_in[9];
    const float* tbias  = (const float*)d_in[10];
    const float* gWi    = (const float*)d_in[11];
    const float* gWh    = (const float*)d_in[12];
    const float* gbi    = (const float*)d_in[13];
    const float* gbh    = (const float*)d_in[14];
    const float* f0w    = (const float*)d_in[15];
    const float* f0b    = (const float*)d_in[16];
    const float* f1w    = (const float*)d_in[17];
    const float* f1b    = (const float*)d_in[18];
    const float* rWi    = (const float*)d_in[19];
    const float* rWh    = (const float*)d_in[20];
    const float* rbi    = (const float*)d_in[21];
    const float* rbh    = (const float*)d_in[22];
    const float* rfw    = (const float*)d_in[23];
    const float* rfb    = (const float*)d_in[24];
    float* out = (float*)d_out;

    float *hcat, *g1f, *g2f, *g1t, *g2t, *xw, *hend, *hrep, *dec;
    cudaGetSymbolAddress((void**)&hcat, g_hcat);
    cudaGetSymbolAddress((void**)&g1f,  g_g1f);
    cudaGetSymbolAddress((void**)&g2f,  g_g2f);
    cudaGetSymbolAddress((void**)&g1t,  g_g1t);
    cudaGetSymbolAddress((void**)&g2t,  g_g2t);
    cudaGetSymbolAddress((void**)&xw,   g_xw);
    cudaGetSymbolAddress((void**)&hend, g_hend);
    cudaGetSymbolAddress((void**)&hrep, g_hrep);
    cudaGetSymbolAddress((void**)&dec,  g_dec);

    const int gru_smem = GRU_SMEM_BYTES;
    cudaFuncSetAttribute(gru_kernel, cudaFuncAttributeMaxDynamicSharedMemorySize, gru_smem);
    cudaFuncSetAttribute(gat_e_feat2_kernel, cudaFuncAttributeMaxDynamicSharedMemorySize, GF_SMEM);
    cudaFuncSetAttribute(gat_e_temp2_kernel, cudaFuncAttributeMaxDynamicSharedMemorySize, GT_SMEM);

    // 1. conv weight transpose + conv -> hcat[:, :, 0:64]
    prep_cwt_kernel<<<(KS_*64*64 + 255)/256, 256>>>(conv_w);
    conv_kernel<<<dim3(32, 16), 512>>>(x, conv_b);

    // 2+3. all four GAT projections in ONE launch (512 CTAs)
    proj4_kernel<<<512, 256>>>(fW, fb, tW, tb);

    // 4. attention e + softmax (SMEM-staged, L2-traffic-free)
    gat_e_feat2_kernel<<<dim3(8, 16), 512, GF_SMEM>>>(g1f, g2f, fa, fbias);
    gat_e_temp2_kernel<<<dim3(8, 16), 512, GT_SMEM>>>(g1t, g2t, ta, tbias);

    // 5. aggregation GEMMs with fused sigmoid -> hcat[64:128], hcat[128:192]
    gatagg_kernel<<<128, 256>>>();

    // 6. encoder xW = hcat @ gWi^T + gbi : [256,192]@[192,450]
    gemm_kernel<<<dim3(8, 4, 16), 256>>>(hcat, 192, 1, 256*192, gWi, 1, 192, gbi, xw, 256*450, 256, 450, 192);
    // 7. encoder GRU -> h_end
    gru_kernel<<<16, 480, gru_smem>>>(xw, gWh, gbh, hend, nullptr);
    // 8. predictions
    pred_kernel<<<16, 192>>>(hend, f0w, f0b, f1w, f1b, out);
    // 9. h_rep
    hrep_kernel<<<(B_*WSZ*HD + 255)/256, 256>>>(hend, hrep);
    // 10. decoder xW = h_rep @ rWi^T + rbi : [256,150]@[150,450]
    gemm_kernel<<<dim3(8, 4, 16), 256>>>(hrep, 150, 1, 256*150, rWi, 1, 150, rbi, xw, 256*450, 256, 450, 150);
    // 11. decoder GRU -> dec_out
    gru_kernel<<<16, 480, gru_smem>>>(xw, rWh, rbh, nullptr, dec);
    // 12. recons = dec_out @ rfw + rfb
    gemm_kernel<<<dim3(1, 4, 16), 256>>>(dec, 150, 1, 256*150, rfw, 64, 1, rfb, out + 1024, 256*64, 256, 64, 150);
}